// round 2
// baseline (speedup 1.0000x reference)
#include <cuda_runtime.h>
#include <cstdint>

#define Bb 8
#define Ll 4096
#define Hh 512
#define Cc 64
#define Aa 512
#define BL (Bb*Ll)           // 32768
#define NEGV (-1000000000.0f)
#define OUT_ATT ((size_t)BL*Hh)   // offset of weights in d_out

// ---------------- scratch (static device globals; no allocation) ----------------
__device__ float g_logits[BL];                 // (B,L)
__device__ float g_x[(size_t)Bb*Cc*Ll];        // (B,C,L) masked channel logits
__device__ float g_ctx[(size_t)Bb*Cc*Hh];      // (B,C,H)
__device__ int   g_hasany[Bb*Cc];
__device__ float g_maxc[Bb];

// ---------------- init logits = score_b + log1p(count) ----------------
__global__ void k_initlogits(const int* __restrict__ cnt, const float* __restrict__ sb) {
    int i = blockIdx.x * 256 + threadIdx.x;
    if (i < BL) {
        int c = cnt[i]; if (c < 0) c = 0;
        g_logits[i] = sb[0] + log1pf((float)c);
    }
}

// ---------------- per-batch max count ----------------
__global__ void k_maxcount(const int* __restrict__ cnt) {
    int b = blockIdx.x;
    __shared__ int r[256];
    int tid = threadIdx.x;
    int mx = 0;
    for (int i = tid; i < Ll; i += 256) mx = max(mx, cnt[b*Ll + i]);
    r[tid] = mx; __syncthreads();
    for (int s = 128; s; s >>= 1) { if (tid < s) r[tid] = max(r[tid], r[tid+s]); __syncthreads(); }
    if (tid == 0) g_maxc[b] = fmaxf((float)r[0], 1.0f);
}

// ---------------- GEMM1: logits += sum_n tanh(h@W + pb)[n] * sw[n] ----------------
__global__ void k_gemm1(const float* __restrict__ Hd, const float* __restrict__ W,
                        const float* __restrict__ pb, const float* __restrict__ sw) {
    __shared__ float As[16][65];   // [k][m]
    __shared__ float Bs[16][64];   // [k][n]
    int m0 = blockIdx.x * 64;
    int n0 = blockIdx.y * 64;
    int tid = threadIdx.x;
    int tx = tid & 15, ty = tid >> 4;
    int arow = tid >> 2, akc = (tid & 3) * 4;
    int brow = tid >> 4, bcol = (tid & 15) * 4;
    float acc[4][4] = {};
    for (int k0 = 0; k0 < Aa; k0 += 16) {
        float4 av = *(const float4*)&Hd[(size_t)(m0 + arow) * Hh + k0 + akc];
        As[akc+0][arow] = av.x; As[akc+1][arow] = av.y;
        As[akc+2][arow] = av.z; As[akc+3][arow] = av.w;
        *(float4*)&Bs[brow][bcol] = *(const float4*)&W[(size_t)(k0 + brow) * Aa + n0 + bcol];
        __syncthreads();
        #pragma unroll
        for (int k = 0; k < 16; k++) {
            float a[4];
            #pragma unroll
            for (int i = 0; i < 4; i++) a[i] = As[k][ty*4+i];
            float4 b4 = *(const float4*)&Bs[k][tx*4];
            float bv[4] = {b4.x, b4.y, b4.z, b4.w};
            #pragma unroll
            for (int i = 0; i < 4; i++)
                #pragma unroll
                for (int j = 0; j < 4; j++)
                    acc[i][j] = fmaf(a[i], bv[j], acc[i][j]);
        }
        __syncthreads();
    }
    float p[4];
    #pragma unroll
    for (int i = 0; i < 4; i++) {
        p[i] = 0.f;
        #pragma unroll
        for (int j = 0; j < 4; j++) {
            int n = n0 + tx*4 + j;
            float t = tanhf(acc[i][j] + pb[n]);
            p[i] = fmaf(t, sw[n], p[i]);
        }
    }
    #pragma unroll
    for (int i = 0; i < 4; i++) {
        #pragma unroll
        for (int off = 8; off; off >>= 1) p[i] += __shfl_down_sync(0xffffffffu, p[i], off, 16);
        if (tx == 0) atomicAdd(&g_logits[m0 + ty*4 + i], p[i]);
    }
}

// ---------------- build masked channel logits, transposed to (B,C,L) ----------------
__global__ void k_chlogits(const float* __restrict__ act) {
    __shared__ float s[64][65];
    int b  = blockIdx.x >> 6;
    int l0 = (blockIdx.x & 63) * 64;
    int tid = threadIdx.x;
    for (int idx = tid; idx < 4096; idx += 256) {
        int l = idx >> 6, c = idx & 63;
        s[l][c] = act[((size_t)(b*Ll + l0 + l)) * Cc + c];
    }
    __syncthreads();
    for (int idx = tid; idx < 4096; idx += 256) {
        int c = idx >> 6, l = idx & 63;
        float a  = s[l][c];
        float lg = g_logits[b*Ll + l0 + l];
        float v  = (a > 0.f) ? (lg + log1pf(a)) : NEGV;
        g_x[((size_t)(b*Cc + c)) * Ll + l0 + l] = v;
    }
}

// ---------------- softmax per (b,c) row, write weights to output ----------------
__global__ void k_softmax(float* __restrict__ wout) {
    int bc = blockIdx.x;
    const float* x = &g_x[(size_t)bc * Ll];
    __shared__ float red[256];
    int tid = threadIdx.x;
    float mx = NEGV;
    for (int i = tid; i < Ll; i += 256) mx = fmaxf(mx, x[i]);
    red[tid] = mx; __syncthreads();
    for (int s = 128; s; s >>= 1) { if (tid < s) red[tid] = fmaxf(red[tid], red[tid+s]); __syncthreads(); }
    mx = red[0]; __syncthreads();
    float sum = 0.f;
    for (int i = tid; i < Ll; i += 256) sum += __expf(x[i] - mx);
    red[tid] = sum; __syncthreads();
    for (int s = 128; s; s >>= 1) { if (tid < s) red[tid] += red[tid+s]; __syncthreads(); }
    sum = red[0];
    int any = mx > -1e8f;
    if (tid == 0) g_hasany[bc] = any;
    float inv = any ? (1.f / sum) : 0.f;
    for (int i = tid; i < Ll; i += 256)
        wout[(size_t)bc * Ll + i] = __expf(x[i] - mx) * inv;
}

// ---------------- zero contexts ----------------
__global__ void k_zeroctx() {
    int i = blockIdx.x * 256 + threadIdx.x;
    if (i < Bb*Cc*Hh) g_ctx[i] = 0.f;
}

// ---------------- contexts: (C x Lchunk) @ (Lchunk x H) per batch, atomic accumulate ----------------
__global__ void k_ctx(const float* __restrict__ Hd, const float* __restrict__ wts) {
    __shared__ float As[16][65];   // [k][c]
    __shared__ float Bs[16][64];   // [k][h]
    int b  = blockIdx.z;
    int h0 = blockIdx.x * 64;
    int l0 = blockIdx.y * 1024;
    int tid = threadIdx.x;
    int tx = tid & 15, ty = tid >> 4;
    int arow = tid >> 2, akc = (tid & 3) * 4;
    int brow = tid >> 4, bcol = (tid & 15) * 4;
    const float* wb = wts + (size_t)b * Cc * Ll;
    const float* hb = Hd  + (size_t)b * Ll * Hh;
    float acc[4][4] = {};
    for (int k0 = 0; k0 < 1024; k0 += 16) {
        float4 av = *(const float4*)&wb[(size_t)arow * Ll + l0 + k0 + akc];
        As[akc+0][arow] = av.x; As[akc+1][arow] = av.y;
        As[akc+2][arow] = av.z; As[akc+3][arow] = av.w;
        *(float4*)&Bs[brow][bcol] = *(const float4*)&hb[(size_t)(l0 + k0 + brow) * Hh + h0 + bcol];
        __syncthreads();
        #pragma unroll
        for (int k = 0; k < 16; k++) {
            float a[4];
            #pragma unroll
            for (int i = 0; i < 4; i++) a[i] = As[k][ty*4+i];
            float4 b4 = *(const float4*)&Bs[k][tx*4];
            float bv[4] = {b4.x, b4.y, b4.z, b4.w};
            #pragma unroll
            for (int i = 0; i < 4; i++)
                #pragma unroll
                for (int j = 0; j < 4; j++)
                    acc[i][j] = fmaf(a[i], bv[j], acc[i][j]);
        }
        __syncthreads();
    }
    #pragma unroll
    for (int i = 0; i < 4; i++)
        #pragma unroll
        for (int j = 0; j < 4; j++)
            atomicAdd(&g_ctx[((size_t)(b*Cc + ty*4 + i)) * Hh + h0 + tx*4 + j], acc[i][j]);
}

// ---------------- fallback for empty channels ----------------
__global__ void k_ctxfix(const float* __restrict__ Hd) {
    int i = blockIdx.x * 256 + threadIdx.x;
    if (i >= Bb*Cc*Hh) return;
    int bc = i >> 9;          // /512
    int h  = i & 511;
    if (!g_hasany[bc]) {
        int b = bc >> 6;
        g_ctx[i] = Hd[((size_t)(b*Ll + (Ll-1))) * Hh + h];
    }
}

// ---------------- final: expanded = mix @ ctx ; gate/mask ----------------
__global__ void k_final(const float* __restrict__ Hd, const float* __restrict__ act,
                        const int* __restrict__ cnt, const int* __restrict__ msk,
                        float* __restrict__ out) {
    __shared__ float s[64][65];    // mix [l][c]
    __shared__ float ct[64][68];   // ctx [c][h]
    int b  = blockIdx.z;
    int h0 = blockIdx.x * 64;
    int l0 = blockIdx.y * 64;
    int tid = threadIdx.x;
    for (int idx = tid; idx < 4096; idx += 256) {
        int l = idx >> 6, c = idx & 63;
        float a = act[((size_t)(b*Ll + l0 + l)) * Cc + c];
        s[l][c] = fmaxf(a, 0.f);
    }
    for (int idx = tid; idx < 4096; idx += 256) {
        int c = idx >> 6, h = idx & 63;
        ct[c][h] = g_ctx[((size_t)(b*Cc + c)) * Hh + h0 + h];
    }
    __syncthreads();
    if (tid < 64) {
        float sum = 0.f;
        #pragma unroll 8
        for (int c = 0; c < 64; c++) sum += s[tid][c];
        float inv = 1.f / fmaxf(sum, 1.f);
        #pragma unroll 8
        for (int c = 0; c < 64; c++) s[tid][c] *= inv;
    }
    __syncthreads();
    int tx = tid & 15, ty = tid >> 4;
    float acc[4][4] = {};
    #pragma unroll 4
    for (int c = 0; c < 64; c++) {
        float a[4];
        #pragma unroll
        for (int i = 0; i < 4; i++) a[i] = s[ty*4+i][c];
        float4 b4 = *(const float4*)&ct[c][tx*4];
        float bv[4] = {b4.x, b4.y, b4.z, b4.w};
        #pragma unroll
        for (int i = 0; i < 4; i++)
            #pragma unroll
            for (int j = 0; j < 4; j++)
                acc[i][j] = fmaf(a[i], bv[j], acc[i][j]);
    }
    #pragma unroll
    for (int i = 0; i < 4; i++) {
        int gi = b*Ll + l0 + ty*4 + i;
        float gate = 1.f + (float)cnt[gi] / g_maxc[b];
        bool m = msk[gi] != 0;
        #pragma unroll
        for (int j = 0; j < 4; j++) {
            size_t o = (size_t)gi * Hh + h0 + tx*4 + j;
            out[o] = m ? acc[i][j] * gate : Hd[o];
        }
    }
}

// ---------------- launch ----------------
extern "C" void kernel_launch(void* const* d_in, const int* in_sizes, int n_in,
                              void* d_out, int out_size) {
    const float* hidden = (const float*)d_in[0];
    const int*   mask   = (const int*)d_in[1];     // bool normalized to int32 by harness
    const int*   cnt    = (const int*)d_in[2];
    const float* act    = (const float*)d_in[3];
    const float* pw     = (const float*)d_in[4];
    const float* pb     = (const float*)d_in[5];
    const float* sw     = (const float*)d_in[6];
    const float* sb     = (const float*)d_in[7];
    float* out  = (float*)d_out;
    float* wout = out + OUT_ATT;

    k_initlogits<<<(BL+255)/256, 256>>>(cnt, sb);
    k_maxcount<<<Bb, 256>>>(cnt);
    k_gemm1<<<dim3(BL/64, Aa/64), 256>>>(hidden, pw, pb, sw);
    k_chlogits<<<Bb*(Ll/64), 256>>>(act);
    k_softmax<<<Bb*Cc, 256>>>(wout);
    k_zeroctx<<<(Bb*Cc*Hh+255)/256, 256>>>();
    k_ctx<<<dim3(Hh/64, Ll/1024, Bb), 256>>>(hidden, wout);
    k_ctxfix<<<(Bb*Cc*Hh+255)/256, 256>>>(hidden);
    k_final<<<dim3(Hh/64, Ll/64, Bb), 256>>>(hidden, act, cnt, mask, out);
}

// round 3
// speedup vs baseline: 1.9725x; 1.9725x over previous
#include <cuda_runtime.h>
#include <cuda_bf16.h>
#include <cstdint>

#define Bb 8
#define Ll 4096
#define Hh 512
#define Cc 64
#define Aa 512
#define BL (Bb*Ll)           // 32768
#define NEGV (-1000000000.0f)
#define OUT_ATT ((size_t)BL*Hh)

// ---------------- scratch (static device globals; no allocation) ----------------
__device__ float g_logits[BL];                 // (B,L)
__device__ float g_x[(size_t)Bb*Cc*Ll];        // (B,C,L) masked channel logits
__device__ float g_ctx[(size_t)Bb*Cc*Hh];      // (B,C,H)
__device__ int   g_hasany[Bb*Cc];
__device__ float g_maxc[Bb];
__device__ __nv_bfloat16 g_hbf[(size_t)BL*Hh];   // hidden in bf16 (32MB)
__device__ __nv_bfloat16 g_wbf_t[(size_t)Aa*Hh]; // proj_w transposed [n][k] bf16

// ---------------- convert hidden to bf16 ----------------
__global__ void k_cvt_h(const float* __restrict__ Hd) {
    size_t i = ((size_t)blockIdx.x * 256 + threadIdx.x) * 4;
    if (i < (size_t)BL*Hh) {
        float4 v = *(const float4*)&Hd[i];
        g_hbf[i+0] = __float2bfloat16(v.x);
        g_hbf[i+1] = __float2bfloat16(v.y);
        g_hbf[i+2] = __float2bfloat16(v.z);
        g_hbf[i+3] = __float2bfloat16(v.w);
    }
}

// ---------------- transpose + convert W: g_wbf_t[n][k] = W[k][n] ----------------
__global__ void k_cvt_wT(const float* __restrict__ W) {
    __shared__ float tile[32][33];
    int tx = threadIdx.x, ty = threadIdx.y;
    int k = blockIdx.x * 32 + ty;
    int n = blockIdx.y * 32 + tx;
    tile[ty][tx] = W[(size_t)k * Aa + n];
    __syncthreads();
    int no = blockIdx.y * 32 + ty;
    int ko = blockIdx.x * 32 + tx;
    g_wbf_t[(size_t)no * Hh + ko] = __float2bfloat16(tile[tx][ty]);
}

// ---------------- init logits = score_b + log1p(count) ----------------
__global__ void k_initlogits(const int* __restrict__ cnt, const float* __restrict__ sb) {
    int i = blockIdx.x * 256 + threadIdx.x;
    if (i < BL) {
        int c = cnt[i]; if (c < 0) c = 0;
        g_logits[i] = sb[0] + log1pf((float)c);
    }
}

// ---------------- per-batch max count ----------------
__global__ void k_maxcount(const int* __restrict__ cnt) {
    int b = blockIdx.x;
    __shared__ int r[256];
    int tid = threadIdx.x;
    int mx = 0;
    for (int i = tid; i < Ll; i += 256) mx = max(mx, cnt[b*Ll + i]);
    r[tid] = mx; __syncthreads();
    for (int s = 128; s; s >>= 1) { if (tid < s) r[tid] = max(r[tid], r[tid+s]); __syncthreads(); }
    if (tid == 0) g_maxc[b] = fmaxf((float)r[0], 1.0f);
}

// ---------------- tensor-core GEMM1: logits += sum_n tanh(h@W + pb)[n]*sw[n] ----------------
__device__ __forceinline__ void mma16816(float* c, const uint32_t* a, const uint32_t* b) {
    asm volatile(
        "mma.sync.aligned.m16n8k16.row.col.f32.bf16.bf16.f32 "
        "{%0,%1,%2,%3}, {%4,%5,%6,%7}, {%8,%9}, {%0,%1,%2,%3};"
        : "+f"(c[0]), "+f"(c[1]), "+f"(c[2]), "+f"(c[3])
        : "r"(a[0]), "r"(a[1]), "r"(a[2]), "r"(a[3]), "r"(b[0]), "r"(b[1]));
}

__global__ __launch_bounds__(256) void k_gemm1_tc(const float* __restrict__ pb,
                                                  const float* __restrict__ sw) {
    __shared__ __nv_bfloat16 As[128][40];   // [m][k] tile, stride 40 -> conflict-free frags
    __shared__ __nv_bfloat16 Bs[128][40];   // [n][k] tile
    int m0 = blockIdx.x * 128, n0 = blockIdx.y * 128;
    int tid = threadIdx.x, lane = tid & 31, wid = tid >> 5;
    int wm = wid >> 1, wn = wid & 1;       // 4x2 warp grid, warp tile 32(m) x 64(n)
    int qr = lane >> 2, qc = (lane & 3) * 2;
    float acc[2][8][4] = {};

    for (int k0 = 0; k0 < Aa; k0 += 32) {
        #pragma unroll
        for (int r2 = 0; r2 < 2; r2++) {
            int row = r2 * 64 + (tid >> 2);
            int seg = (tid & 3) * 8;
            *(float4*)&As[row][seg] = *(const float4*)&g_hbf[(size_t)(m0 + row) * Hh + k0 + seg];
            *(float4*)&Bs[row][seg] = *(const float4*)&g_wbf_t[(size_t)(n0 + row) * Hh + k0 + seg];
        }
        __syncthreads();
        #pragma unroll
        for (int ks = 0; ks < 32; ks += 16) {
            uint32_t af[2][4], bf[8][2];
            #pragma unroll
            for (int mi = 0; mi < 2; mi++) {
                int r = wm * 32 + mi * 16 + qr;
                af[mi][0] = *(const uint32_t*)&As[r    ][ks + qc];
                af[mi][1] = *(const uint32_t*)&As[r + 8][ks + qc];
                af[mi][2] = *(const uint32_t*)&As[r    ][ks + qc + 8];
                af[mi][3] = *(const uint32_t*)&As[r + 8][ks + qc + 8];
            }
            #pragma unroll
            for (int ni = 0; ni < 8; ni++) {
                int n = wn * 64 + ni * 8 + qr;
                bf[ni][0] = *(const uint32_t*)&Bs[n][ks + qc];
                bf[ni][1] = *(const uint32_t*)&Bs[n][ks + qc + 8];
            }
            #pragma unroll
            for (int mi = 0; mi < 2; mi++)
                #pragma unroll
                for (int ni = 0; ni < 8; ni++)
                    mma16816(acc[mi][ni], af[mi], bf[ni]);
        }
        __syncthreads();
    }

    // epilogue: tanh + dot(sw), reduce cols, atomic row add
    float pbv[8][2], swv[8][2];
    #pragma unroll
    for (int ni = 0; ni < 8; ni++) {
        int n = n0 + wn * 64 + ni * 8 + qc;
        pbv[ni][0] = pb[n]; pbv[ni][1] = pb[n + 1];
        swv[ni][0] = sw[n]; swv[ni][1] = sw[n + 1];
    }
    #pragma unroll
    for (int mi = 0; mi < 2; mi++) {
        float p0 = 0.f, p1 = 0.f;
        #pragma unroll
        for (int ni = 0; ni < 8; ni++) {
            p0 += tanhf(acc[mi][ni][0] + pbv[ni][0]) * swv[ni][0];
            p0 += tanhf(acc[mi][ni][1] + pbv[ni][1]) * swv[ni][1];
            p1 += tanhf(acc[mi][ni][2] + pbv[ni][0]) * swv[ni][0];
            p1 += tanhf(acc[mi][ni][3] + pbv[ni][1]) * swv[ni][1];
        }
        p0 += __shfl_xor_sync(0xffffffffu, p0, 1); p0 += __shfl_xor_sync(0xffffffffu, p0, 2);
        p1 += __shfl_xor_sync(0xffffffffu, p1, 1); p1 += __shfl_xor_sync(0xffffffffu, p1, 2);
        if ((lane & 3) == 0) {
            int r = m0 + wm * 32 + mi * 16 + qr;
            atomicAdd(&g_logits[r], p0);
            atomicAdd(&g_logits[r + 8], p1);
        }
    }
}

// ---------------- build masked channel logits, transposed to (B,C,L) ----------------
__global__ void k_chlogits(const float* __restrict__ act) {
    __shared__ float s[64][65];
    int b  = blockIdx.x >> 6;
    int l0 = (blockIdx.x & 63) * 64;
    int tid = threadIdx.x;
    for (int idx = tid; idx < 4096; idx += 256) {
        int l = idx >> 6, c = idx & 63;
        s[l][c] = act[((size_t)(b*Ll + l0 + l)) * Cc + c];
    }
    __syncthreads();
    for (int idx = tid; idx < 4096; idx += 256) {
        int c = idx >> 6, l = idx & 63;
        float a  = s[l][c];
        float lg = g_logits[b*Ll + l0 + l];
        float v  = (a > 0.f) ? (lg + log1pf(a)) : NEGV;
        g_x[((size_t)(b*Cc + c)) * Ll + l0 + l] = v;
    }
}

// ---------------- softmax per (b,c) row: exp cached in wout ----------------
__global__ void k_softmax(float* __restrict__ wout) {
    int bc = blockIdx.x;
    const float* x = &g_x[(size_t)bc * Ll];
    float* w = &wout[(size_t)bc * Ll];
    __shared__ float red[256];
    int tid = threadIdx.x;
    float mx = NEGV;
    for (int i = tid; i < Ll; i += 256) mx = fmaxf(mx, x[i]);
    red[tid] = mx; __syncthreads();
    for (int s = 128; s; s >>= 1) { if (tid < s) red[tid] = fmaxf(red[tid], red[tid+s]); __syncthreads(); }
    mx = red[0]; __syncthreads();
    float sum = 0.f;
    for (int i = tid; i < Ll; i += 256) {
        float e = __expf(x[i] - mx);
        w[i] = e;
        sum += e;
    }
    red[tid] = sum; __syncthreads();
    for (int s = 128; s; s >>= 1) { if (tid < s) red[tid] += red[tid+s]; __syncthreads(); }
    sum = red[0];
    int any = mx > -1e8f;
    if (tid == 0) g_hasany[bc] = any;
    float inv = any ? (1.f / sum) : 0.f;
    for (int i = tid; i < Ll; i += 256) w[i] *= inv;
}

// ---------------- zero contexts ----------------
__global__ void k_zeroctx() {
    int i = blockIdx.x * 256 + threadIdx.x;
    if (i < Bb*Cc*Hh) g_ctx[i] = 0.f;
}

// ---------------- contexts: (C x Lchunk) @ (Lchunk x H), atomic accumulate ----------------
__global__ void k_ctx(const float* __restrict__ Hd, const float* __restrict__ wts) {
    __shared__ float As[16][65];   // [k][c]
    __shared__ float Bs[16][64];   // [k][h]
    int b  = blockIdx.z;
    int h0 = blockIdx.x * 64;
    int l0 = blockIdx.y * 1024;
    int tid = threadIdx.x;
    int tx = tid & 15, ty = tid >> 4;
    int arow = tid >> 2, akc = (tid & 3) * 4;
    int brow = tid >> 4, bcol = (tid & 15) * 4;
    const float* wb = wts + (size_t)b * Cc * Ll;
    const float* hb = Hd  + (size_t)b * Ll * Hh;
    float acc[4][4] = {};
    for (int k0 = 0; k0 < 1024; k0 += 16) {
        float4 av = *(const float4*)&wb[(size_t)arow * Ll + l0 + k0 + akc];
        As[akc+0][arow] = av.x; As[akc+1][arow] = av.y;
        As[akc+2][arow] = av.z; As[akc+3][arow] = av.w;
        *(float4*)&Bs[brow][bcol] = *(const float4*)&hb[(size_t)(l0 + k0 + brow) * Hh + h0 + bcol];
        __syncthreads();
        #pragma unroll
        for (int k = 0; k < 16; k++) {
            float a[4];
            #pragma unroll
            for (int i = 0; i < 4; i++) a[i] = As[k][ty*4+i];
            float4 b4 = *(const float4*)&Bs[k][tx*4];
            float bv[4] = {b4.x, b4.y, b4.z, b4.w};
            #pragma unroll
            for (int i = 0; i < 4; i++)
                #pragma unroll
                for (int j = 0; j < 4; j++)
                    acc[i][j] = fmaf(a[i], bv[j], acc[i][j]);
        }
        __syncthreads();
    }
    #pragma unroll
    for (int i = 0; i < 4; i++)
        #pragma unroll
        for (int j = 0; j < 4; j++)
            atomicAdd(&g_ctx[((size_t)(b*Cc + ty*4 + i)) * Hh + h0 + tx*4 + j], acc[i][j]);
}

// ---------------- fallback for empty channels ----------------
__global__ void k_ctxfix(const float* __restrict__ Hd) {
    int i = blockIdx.x * 256 + threadIdx.x;
    if (i >= Bb*Cc*Hh) return;
    int bc = i >> 9;
    int h  = i & 511;
    if (!g_hasany[bc]) {
        int b = bc >> 6;
        g_ctx[i] = Hd[((size_t)(b*Ll + (Ll-1))) * Hh + h];
    }
}

// ---------------- final: expanded = mix @ ctx ; gate/mask ----------------
__global__ void k_final(const float* __restrict__ Hd, const float* __restrict__ act,
                        const int* __restrict__ cnt, const int* __restrict__ msk,
                        float* __restrict__ out) {
    __shared__ float s[64][65];    // mix [l][c]
    __shared__ float ct[64][68];   // ctx [c][h]
    int b  = blockIdx.z;
    int h0 = blockIdx.x * 64;
    int l0 = blockIdx.y * 64;
    int tid = threadIdx.x;
    for (int idx = tid; idx < 4096; idx += 256) {
        int l = idx >> 6, c = idx & 63;
        float a = act[((size_t)(b*Ll + l0 + l)) * Cc + c];
        s[l][c] = fmaxf(a, 0.f);
    }
    for (int idx = tid; idx < 4096; idx += 256) {
        int c = idx >> 6, h = idx & 63;
        ct[c][h] = g_ctx[((size_t)(b*Cc + c)) * Hh + h0 + h];
    }
    __syncthreads();
    if (tid < 64) {
        float sum = 0.f;
        #pragma unroll 8
        for (int c = 0; c < 64; c++) sum += s[tid][c];
        float inv = 1.f / fmaxf(sum, 1.f);
        #pragma unroll 8
        for (int c = 0; c < 64; c++) s[tid][c] *= inv;
    }
    __syncthreads();
    int tx = tid & 15, ty = tid >> 4;
    float acc[4][4] = {};
    #pragma unroll 4
    for (int c = 0; c < 64; c++) {
        float a[4];
        #pragma unroll
        for (int i = 0; i < 4; i++) a[i] = s[ty*4+i][c];
        float4 b4 = *(const float4*)&ct[c][tx*4];
        float bv[4] = {b4.x, b4.y, b4.z, b4.w};
        #pragma unroll
        for (int i = 0; i < 4; i++)
            #pragma unroll
            for (int j = 0; j < 4; j++)
                acc[i][j] = fmaf(a[i], bv[j], acc[i][j]);
    }
    #pragma unroll
    for (int i = 0; i < 4; i++) {
        int gi = b*Ll + l0 + ty*4 + i;
        float gate = 1.f + (float)cnt[gi] / g_maxc[b];
        bool m = msk[gi] != 0;
        #pragma unroll
        for (int j = 0; j < 4; j++) {
            size_t o = (size_t)gi * Hh + h0 + tx*4 + j;
            out[o] = m ? acc[i][j] * gate : Hd[o];
        }
    }
}

// ---------------- launch ----------------
extern "C" void kernel_launch(void* const* d_in, const int* in_sizes, int n_in,
                              void* d_out, int out_size) {
    const float* hidden = (const float*)d_in[0];
    const int*   mask   = (const int*)d_in[1];
    const int*   cnt    = (const int*)d_in[2];
    const float* act    = (const float*)d_in[3];
    const float* pw     = (const float*)d_in[4];
    const float* pb     = (const float*)d_in[5];
    const float* sw     = (const float*)d_in[6];
    const float* sb     = (const float*)d_in[7];
    float* out  = (float*)d_out;
    float* wout = out + OUT_ATT;

    k_cvt_h<<<(BL*Hh/4 + 255)/256, 256>>>(hidden);
    k_cvt_wT<<<dim3(Aa/32, Aa/32), dim3(32,32)>>>(pw);
    k_initlogits<<<(BL+255)/256, 256>>>(cnt, sb);
    k_maxcount<<<Bb, 256>>>(cnt);
    k_gemm1_tc<<<dim3(BL/128, Aa/128), 256>>>(pb, sw);
    k_chlogits<<<Bb*(Ll/64), 256>>>(act);
    k_softmax<<<Bb*Cc, 256>>>(wout);
    k_zeroctx<<<(Bb*Cc*Hh+255)/256, 256>>>();
    k_ctx<<<dim3(Hh/64, Ll/1024, Bb), 256>>>(hidden, wout);
    k_ctxfix<<<(Bb*Cc*Hh+255)/256, 256>>>(hidden);
    k_final<<<dim3(Hh/64, Ll/64, Bb), 256>>>(hidden, act, cnt, mask, out);
}

// round 4
// speedup vs baseline: 2.0743x; 1.0516x over previous
#include <cuda_runtime.h>
#include <cuda_bf16.h>
#include <cstdint>

#define Bb 8
#define Ll 4096
#define Hh 512
#define Cc 64
#define Aa 512
#define BL (Bb*Ll)
#define NEGV (-1000000000.0f)
#define OUT_ATT ((size_t)BL*Hh)

#define AS_STRIDE 520
#define BS_STRIDE 72
#define GEMM_SMEM (64*AS_STRIDE*2 + 2*128*BS_STRIDE*2)   // 66560 + 36864 = 103424

// ---------------- scratch ----------------
__device__ float g_logits[BL];
__device__ float g_x[(size_t)Bb*Cc*Ll];
__device__ float g_ctx[(size_t)Bb*Cc*Hh];
__device__ int   g_hasany[Bb*Cc];
__device__ int   g_maxi[Bb];                       // idempotent atomicMax accumulator
__device__ __nv_bfloat16 g_wbf_t[(size_t)Aa*Hh];   // proj_w transposed [n][k] bf16

// ---------------- helpers ----------------
__device__ __forceinline__ uint32_t smem_u32(const void* p) {
    uint32_t a;
    asm("{ .reg .u64 t; cvta.to.shared.u64 t, %1; cvt.u32.u64 %0, t; }" : "=r"(a) : "l"(p));
    return a;
}
__device__ __forceinline__ void cpasync16(void* dst, const void* src) {
    asm volatile("cp.async.cg.shared.global [%0], [%1], 16;" :: "r"(smem_u32(dst)), "l"(src));
}
__device__ __forceinline__ void cp_commit() { asm volatile("cp.async.commit_group;"); }
template<int N> __device__ __forceinline__ void cp_wait() {
    asm volatile("cp.async.wait_group %0;" :: "n"(N));
}
__device__ __forceinline__ void mma16816(float* c, const uint32_t* a, const uint32_t* b) {
    asm volatile(
        "mma.sync.aligned.m16n8k16.row.col.f32.bf16.bf16.f32 "
        "{%0,%1,%2,%3}, {%4,%5,%6,%7}, {%8,%9}, {%0,%1,%2,%3};"
        : "+f"(c[0]), "+f"(c[1]), "+f"(c[2]), "+f"(c[3])
        : "r"(a[0]), "r"(a[1]), "r"(a[2]), "r"(a[3]), "r"(b[0]), "r"(b[1]));
}

// ---------------- transpose + convert W: g_wbf_t[n][k] = W[k][n] ----------------
__global__ void k_cvt_wT(const float* __restrict__ W) {
    __shared__ float tile[32][33];
    int tx = threadIdx.x, ty = threadIdx.y;
    int k = blockIdx.x * 32 + ty;
    int n = blockIdx.y * 32 + tx;
    tile[ty][tx] = W[(size_t)k * Aa + n];
    __syncthreads();
    int no = blockIdx.y * 32 + ty;
    int ko = blockIdx.x * 32 + tx;
    g_wbf_t[(size_t)no * Hh + ko] = __float2bfloat16(tile[tx][ty]);
}

// ---------------- per-batch max count (idempotent atomicMax) ----------------
__global__ void k_maxcount(const int* __restrict__ cnt) {
    int b = blockIdx.x >> 3, seg = blockIdx.x & 7;
    int v = cnt[b*Ll + seg*512 + threadIdx.x];
    #pragma unroll
    for (int o = 16; o; o >>= 1) v = max(v, __shfl_xor_sync(0xffffffffu, v, o));
    if ((threadIdx.x & 31) == 0) atomicMax(&g_maxi[b], v);
}

// ---------------- GEMM1 v2: A-resident, pipelined, fused epilogue ----------------
extern __shared__ char smem_raw[];

__global__ __launch_bounds__(256) void k_gemm1_v2(const float* __restrict__ Hd,
                                                  const float* __restrict__ pb,
                                                  const float* __restrict__ sw,
                                                  const int* __restrict__ cnt,
                                                  const float* __restrict__ sb) {
    __nv_bfloat16 (*As)[AS_STRIDE] = (__nv_bfloat16(*)[AS_STRIDE])smem_raw;
    __nv_bfloat16 (*Bs)[128][BS_STRIDE] =
        (__nv_bfloat16(*)[128][BS_STRIDE])(smem_raw + 64*AS_STRIDE*2);
    float (*red)[5] = (float(*)[5])(smem_raw + 64*AS_STRIDE*2);   // aliases Bs (used after)

    int m0 = blockIdx.x * 64;
    int tid = threadIdx.x, lane = tid & 31, wid = tid >> 5;
    int wm = wid >> 2, wn = wid & 3;     // 2(m) x 4(n); warp tile 32m x 32n
    int qr = lane >> 2, qc = (lane & 3) * 2;

    // issue first B chunk (nc=0, k0=0) while A loads
    {
        #pragma unroll
        for (int u = 0; u < 4; u++) {
            int unit = tid * 4 + u;
            int row = unit >> 3, cu = unit & 7;
            cpasync16(&Bs[0][row][cu*8], &g_wbf_t[(size_t)row * Hh + cu*8]);
        }
        cp_commit();
    }
    // load A (f32 -> bf16) fully resident
    for (int i = tid; i < 64*512/4; i += 256) {
        int e = i * 4, row = e >> 9, col = e & 511;
        float4 v = *(const float4*)&Hd[(size_t)(m0 + row) * Hh + col];
        __nv_bfloat162* p = (__nv_bfloat162*)&As[row][col];
        p[0] = __floats2bfloat162_rn(v.x, v.y);
        p[1] = __floats2bfloat162_rn(v.z, v.w);
    }

    float psum[2][2] = {};
    for (int nc = 0; nc < 4; nc++) {
        int n0 = nc * 128;
        float acc[2][4][4] = {};
        for (int kc = 0; kc < 8; kc++) {
            // issue next chunk
            int nn0 = n0, nk0 = (kc + 1) * 64;
            bool more = true;
            if (kc == 7) { if (nc < 3) { nn0 = n0 + 128; nk0 = 0; } else more = false; }
            if (more) {
                int buf = (kc + 1) & 1;
                #pragma unroll
                for (int u = 0; u < 4; u++) {
                    int unit = tid * 4 + u;
                    int row = unit >> 3, cu = unit & 7;
                    cpasync16(&Bs[buf][row][cu*8],
                              &g_wbf_t[(size_t)(nn0 + row) * Hh + nk0 + cu*8]);
                }
                cp_commit();
                cp_wait<1>();
            } else {
                cp_wait<0>();
            }
            __syncthreads();
            int cur = kc & 1;
            #pragma unroll
            for (int ks0 = 0; ks0 < 64; ks0 += 16) {
                int kk = kc * 64 + ks0;
                uint32_t af[2][4], bf[4][2];
                #pragma unroll
                for (int mi = 0; mi < 2; mi++) {
                    int r = wm * 32 + mi * 16 + qr;
                    af[mi][0] = *(const uint32_t*)&As[r    ][kk + qc];
                    af[mi][1] = *(const uint32_t*)&As[r + 8][kk + qc];
                    af[mi][2] = *(const uint32_t*)&As[r    ][kk + qc + 8];
                    af[mi][3] = *(const uint32_t*)&As[r + 8][kk + qc + 8];
                }
                #pragma unroll
                for (int ni = 0; ni < 4; ni++) {
                    int n = wn * 32 + ni * 8 + qr;
                    bf[ni][0] = *(const uint32_t*)&Bs[cur][n][ks0 + qc];
                    bf[ni][1] = *(const uint32_t*)&Bs[cur][n][ks0 + qc + 8];
                }
                #pragma unroll
                for (int mi = 0; mi < 2; mi++)
                    #pragma unroll
                    for (int ni = 0; ni < 4; ni++)
                        mma16816(acc[mi][ni], af[mi], bf[ni]);
            }
            __syncthreads();
        }
        // partial epilogue for this n-chunk
        #pragma unroll
        for (int mi = 0; mi < 2; mi++)
            #pragma unroll
            for (int ni = 0; ni < 4; ni++) {
                int n = n0 + wn * 32 + ni * 8 + qc;
                float pb0 = pb[n], pb1 = pb[n+1], sw0 = sw[n], sw1 = sw[n+1];
                psum[mi][0] += tanhf(acc[mi][ni][0] + pb0) * sw0
                             + tanhf(acc[mi][ni][1] + pb1) * sw1;
                psum[mi][1] += tanhf(acc[mi][ni][2] + pb0) * sw0
                             + tanhf(acc[mi][ni][3] + pb1) * sw1;
            }
    }
    // reduce across quad lanes
    #pragma unroll
    for (int mi = 0; mi < 2; mi++)
        #pragma unroll
        for (int j = 0; j < 2; j++) {
            psum[mi][j] += __shfl_xor_sync(0xffffffffu, psum[mi][j], 1);
            psum[mi][j] += __shfl_xor_sync(0xffffffffu, psum[mi][j], 2);
        }
    if ((lane & 3) == 0) {
        #pragma unroll
        for (int mi = 0; mi < 2; mi++) {
            red[wm*32 + mi*16 + qr    ][wn] = psum[mi][0];
            red[wm*32 + mi*16 + qr + 8][wn] = psum[mi][1];
        }
    }
    __syncthreads();
    if (tid < 64) {
        float s = red[tid][0] + red[tid][1] + red[tid][2] + red[tid][3];
        int c = cnt[m0 + tid]; if (c < 0) c = 0;
        g_logits[m0 + tid] = sb[0] + log1pf((float)c) + s;
    }
}

// ---------------- masked channel logits, transposed to (B,C,L) ----------------
__global__ void k_chlogits(const float* __restrict__ act) {
    __shared__ float s[64][65];
    int b  = blockIdx.x >> 6;
    int l0 = (blockIdx.x & 63) * 64;
    int tid = threadIdx.x;
    for (int idx = tid; idx < 4096; idx += 256) {
        int l = idx >> 6, c = idx & 63;
        s[l][c] = act[((size_t)(b*Ll + l0 + l)) * Cc + c];
    }
    __syncthreads();
    for (int idx = tid; idx < 4096; idx += 256) {
        int c = idx >> 6, l = idx & 63;
        float a  = s[l][c];
        float lg = g_logits[b*Ll + l0 + l];
        float v  = (a > 0.f) ? (lg + log1pf(a)) : NEGV;
        g_x[((size_t)(b*Cc + c)) * Ll + l0 + l] = v;
    }
}

// ---------------- softmax per (b,c) row ----------------
__global__ void k_softmax(float* __restrict__ wout) {
    int bc = blockIdx.x;
    const float* x = &g_x[(size_t)bc * Ll];
    float* w = &wout[(size_t)bc * Ll];
    __shared__ float red[256];
    int tid = threadIdx.x;
    float mx = NEGV;
    for (int i = tid; i < Ll; i += 256) mx = fmaxf(mx, x[i]);
    red[tid] = mx; __syncthreads();
    for (int s = 128; s; s >>= 1) { if (tid < s) red[tid] = fmaxf(red[tid], red[tid+s]); __syncthreads(); }
    mx = red[0]; __syncthreads();
    float sum = 0.f;
    for (int i = tid; i < Ll; i += 256) {
        float e = __expf(x[i] - mx);
        w[i] = e;
        sum += e;
    }
    red[tid] = sum; __syncthreads();
    for (int s = 128; s; s >>= 1) { if (tid < s) red[tid] += red[tid+s]; __syncthreads(); }
    sum = red[0];
    int any = mx > -1e8f;
    if (tid == 0) g_hasany[bc] = any;
    float inv = any ? (1.f / sum) : 0.f;
    for (int i = tid; i < Ll; i += 256) w[i] *= inv;
}

// ---------------- zero contexts ----------------
__global__ void k_zeroctx() {
    int i = blockIdx.x * 256 + threadIdx.x;
    if (i < Bb*Cc*Hh) g_ctx[i] = 0.f;
}

// ---------------- contexts ----------------
__global__ void k_ctx(const float* __restrict__ Hd, const float* __restrict__ wts) {
    __shared__ float As2[16][65];
    __shared__ float Bs2[16][64];
    int b  = blockIdx.z;
    int h0 = blockIdx.x * 64;
    int l0 = blockIdx.y * 1024;
    int tid = threadIdx.x;
    int tx = tid & 15, ty = tid >> 4;
    int arow = tid >> 2, akc = (tid & 3) * 4;
    int brow = tid >> 4, bcol = (tid & 15) * 4;
    const float* wb = wts + (size_t)b * Cc * Ll;
    const float* hb = Hd  + (size_t)b * Ll * Hh;
    float acc[4][4] = {};
    for (int k0 = 0; k0 < 1024; k0 += 16) {
        float4 av = *(const float4*)&wb[(size_t)arow * Ll + l0 + k0 + akc];
        As2[akc+0][arow] = av.x; As2[akc+1][arow] = av.y;
        As2[akc+2][arow] = av.z; As2[akc+3][arow] = av.w;
        *(float4*)&Bs2[brow][bcol] = *(const float4*)&hb[(size_t)(l0 + k0 + brow) * Hh + h0 + bcol];
        __syncthreads();
        #pragma unroll
        for (int k = 0; k < 16; k++) {
            float a[4];
            #pragma unroll
            for (int i = 0; i < 4; i++) a[i] = As2[k][ty*4+i];
            float4 b4 = *(const float4*)&Bs2[k][tx*4];
            float bv[4] = {b4.x, b4.y, b4.z, b4.w};
            #pragma unroll
            for (int i = 0; i < 4; i++)
                #pragma unroll
                for (int j = 0; j < 4; j++)
                    acc[i][j] = fmaf(a[i], bv[j], acc[i][j]);
        }
        __syncthreads();
    }
    #pragma unroll
    for (int i = 0; i < 4; i++)
        #pragma unroll
        for (int j = 0; j < 4; j++)
            atomicAdd(&g_ctx[((size_t)(b*Cc + ty*4 + i)) * Hh + h0 + tx*4 + j], acc[i][j]);
}

// ---------------- fallback for empty channels ----------------
__global__ void k_ctxfix(const float* __restrict__ Hd) {
    int i = blockIdx.x * 256 + threadIdx.x;
    if (i >= Bb*Cc*Hh) return;
    int bc = i >> 9;
    int h  = i & 511;
    if (!g_hasany[bc]) {
        int b = bc >> 6;
        g_ctx[i] = Hd[((size_t)(b*Ll + (Ll-1))) * Hh + h];
    }
}

// ---------------- final v2: per (b, l-tile), loop h ----------------
__global__ __launch_bounds__(256) void k_final2(const float* __restrict__ Hd,
                                                const float* __restrict__ act,
                                                const int* __restrict__ cnt,
                                                const int* __restrict__ msk,
                                                float* __restrict__ out) {
    __shared__ float s[64][65];
    __shared__ float ct[64][68];
    __shared__ float gate[64];
    __shared__ int   mk[64];
    int b  = blockIdx.y;
    int l0 = blockIdx.x * 64;
    int tid = threadIdx.x;
    for (int idx = tid; idx < 4096; idx += 256) {
        int l = idx >> 6, c = idx & 63;
        float a = act[((size_t)(b*Ll + l0 + l)) * Cc + c];
        s[l][c] = fmaxf(a, 0.f);
    }
    __syncthreads();
    if (tid < 64) {
        float sum = 0.f;
        #pragma unroll 8
        for (int c = 0; c < 64; c++) sum += s[tid][c];
        float inv = 1.f / fmaxf(sum, 1.f);
        #pragma unroll 8
        for (int c = 0; c < 64; c++) s[tid][c] *= inv;
        int gi = b*Ll + l0 + tid;
        gate[tid] = 1.f + (float)cnt[gi] / fmaxf((float)g_maxi[b], 1.f);
        mk[tid] = msk[gi];
    }
    __syncthreads();
    int tx = tid & 15, ty = tid >> 4;
    for (int h0 = 0; h0 < Hh; h0 += 64) {
        for (int idx = tid; idx < 4096; idx += 256) {
            int c = idx >> 6, h = idx & 63;
            ct[c][h] = g_ctx[((size_t)(b*Cc + c)) * Hh + h0 + h];
        }
        __syncthreads();
        float acc[4][4] = {};
        #pragma unroll 4
        for (int c = 0; c < 64; c++) {
            float a[4];
            #pragma unroll
            for (int i = 0; i < 4; i++) a[i] = s[ty*4+i][c];
            float4 b4 = *(const float4*)&ct[c][tx*4];
            float bv[4] = {b4.x, b4.y, b4.z, b4.w};
            #pragma unroll
            for (int i = 0; i < 4; i++)
                #pragma unroll
                for (int j = 0; j < 4; j++)
                    acc[i][j] = fmaf(a[i], bv[j], acc[i][j]);
        }
        #pragma unroll
        for (int i = 0; i < 4; i++) {
            int l = ty*4 + i;
            int gi = b*Ll + l0 + l;
            float g = gate[l];
            bool m = mk[l] != 0;
            #pragma unroll
            for (int j = 0; j < 4; j++) {
                size_t o = (size_t)gi * Hh + h0 + tx*4 + j;
                out[o] = m ? acc[i][j] * g : Hd[o];
            }
        }
        __syncthreads();
    }
}

// ---------------- launch ----------------
extern "C" void kernel_launch(void* const* d_in, const int* in_sizes, int n_in,
                              void* d_out, int out_size) {
    const float* hidden = (const float*)d_in[0];
    const int*   mask   = (const int*)d_in[1];
    const int*   cnt    = (const int*)d_in[2];
    const float* act    = (const float*)d_in[3];
    const float* pw     = (const float*)d_in[4];
    const float* pb     = (const float*)d_in[5];
    const float* sw     = (const float*)d_in[6];
    const float* sb     = (const float*)d_in[7];
    float* out  = (float*)d_out;
    float* wout = out + OUT_ATT;

    static bool attr_done = false;
    if (!attr_done) {
        cudaFuncSetAttribute(k_gemm1_v2, cudaFuncAttributeMaxDynamicSharedMemorySize, GEMM_SMEM);
        attr_done = true;
    }

    k_cvt_wT<<<dim3(Aa/32, Aa/32), dim3(32,32)>>>(pw);
    k_maxcount<<<Bb*8, 512>>>(cnt);
    k_gemm1_v2<<<BL/64, 256, GEMM_SMEM>>>(hidden, pb, sw, cnt, sb);
    k_chlogits<<<Bb*(Ll/64), 256>>>(act);
    k_softmax<<<Bb*Cc, 256>>>(wout);
    k_zeroctx<<<(Bb*Cc*Hh+255)/256, 256>>>();
    k_ctx<<<dim3(Hh/64, Ll/1024, Bb), 256>>>(hidden, wout);
    k_ctxfix<<<(Bb*Cc*Hh+255)/256, 256>>>(hidden);
    k_final2<<<dim3(Ll/64, Bb), 256>>>(hidden, act, cnt, mask, out);
}

// round 6
// speedup vs baseline: 2.2700x; 1.0944x over previous
#include <cuda_runtime.h>
#include <cuda_bf16.h>
#include <cuda_fp16.h>
#include <cstdint>

#define Bb 8
#define Ll 4096
#define Hh 512
#define Cc 64
#define Aa 512
#define BL (Bb*Ll)
#define NEGV (-1000000000.0f)
#define OUT_ATT ((size_t)BL*Hh)

// ---- GEMM1 config: 128m per CTA, A resident, B double-buffered ----
#define GM 128
#define ABYTES (128*1024)          // 128 rows x 512 bf16
#define BROW 80                    // padded row pitch for B tile (32k x 2B = 64B data)
#define BSZ (128*BROW)             // 10240
#define SM_B ABYTES
#define GEMM_SMEM (ABYTES + 2*BSZ) // 151552

// ---------------- scratch ----------------
__device__ float g_logits[BL];
__device__ float g_x[(size_t)Bb*Cc*Ll];
__device__ float g_ctx[(size_t)Bb*Cc*Hh];
__device__ int   g_hasany[Bb*Cc];
__device__ int   g_maxi[Bb];
__device__ __nv_bfloat16 g_wbf_t[(size_t)Aa*Hh];   // proj_w transposed [n][k] bf16

// ---------------- helpers ----------------
__device__ __forceinline__ uint32_t smem_u32(const void* p) {
    uint32_t a;
    asm("{ .reg .u64 t; cvta.to.shared.u64 t, %1; cvt.u32.u64 %0, t; }" : "=r"(a) : "l"(p));
    return a;
}
__device__ __forceinline__ void cpasync16(uint32_t dst, const void* src) {
    asm volatile("cp.async.cg.shared.global [%0], [%1], 16;" :: "r"(dst), "l"(src));
}
__device__ __forceinline__ void cp_commit() { asm volatile("cp.async.commit_group;"); }
template<int N> __device__ __forceinline__ void cp_wait() {
    asm volatile("cp.async.wait_group %0;" :: "n"(N));
}
__device__ __forceinline__ void ldsm_x4(uint32_t* r, uint32_t addr) {
    asm volatile("ldmatrix.sync.aligned.m8n8.x4.shared.b16 {%0,%1,%2,%3}, [%4];"
        : "=r"(r[0]), "=r"(r[1]), "=r"(r[2]), "=r"(r[3]) : "r"(addr));
}
__device__ __forceinline__ void mma16816(float* c, const uint32_t* a, const uint32_t* b) {
    asm volatile(
        "mma.sync.aligned.m16n8k16.row.col.f32.bf16.bf16.f32 "
        "{%0,%1,%2,%3}, {%4,%5,%6,%7}, {%8,%9}, {%0,%1,%2,%3};"
        : "+f"(c[0]), "+f"(c[1]), "+f"(c[2]), "+f"(c[3])
        : "r"(a[0]), "r"(a[1]), "r"(a[2]), "r"(a[3]), "r"(b[0]), "r"(b[1]));
}
__device__ __forceinline__ uint32_t tanh2(uint32_t x) {
    uint32_t r;
    asm("tanh.approx.f16x2 %0, %1;" : "=r"(r) : "r"(x));
    return r;
}

// ---------------- transpose + convert W: g_wbf_t[n][k] = W[k][n] ----------------
__global__ void k_cvt_wT(const float* __restrict__ W) {
    __shared__ float tile[32][33];
    int tx = threadIdx.x, ty = threadIdx.y;
    int k = blockIdx.x * 32 + ty;
    int n = blockIdx.y * 32 + tx;
    tile[ty][tx] = W[(size_t)k * Aa + n];
    __syncthreads();
    int no = blockIdx.y * 32 + ty;
    int ko = blockIdx.x * 32 + tx;
    g_wbf_t[(size_t)no * Hh + ko] = __float2bfloat16(tile[tx][ty]);
}

// ---------------- per-batch max count ----------------
__global__ void k_maxcount(const int* __restrict__ cnt) {
    int b = blockIdx.x >> 3, seg = blockIdx.x & 7;
    int v = cnt[b*Ll + seg*512 + threadIdx.x];
    #pragma unroll
    for (int o = 16; o; o >>= 1) v = max(v, __shfl_xor_sync(0xffffffffu, v, o));
    if ((threadIdx.x & 31) == 0) atomicMax(&g_maxi[b], v);
}

// ---------------- GEMM1 v3: ldmatrix HMMA + f16x2 tanh epilogue ----------------
extern __shared__ char smem_raw[];

__global__ __launch_bounds__(256)
void k_gemm1_v3(const float* __restrict__ Hd,
                const float* __restrict__ pb, const float* __restrict__ sw,
                const int* __restrict__ cnt, const float* __restrict__ sb) {
    uint32_t smem_base = smem_u32(smem_raw);
    int tid = threadIdx.x, lane = tid & 31, wid = tid >> 5;
    int wm = wid >> 2, wn = wid & 3;      // 2m x 4n warps; warp tile 64m x 32n
    int m0 = blockIdx.x * GM;

    // prefetch B chunk 0 (nc=0, kc=0)
    #pragma unroll
    for (int u = 0; u < 2; u++) {
        int e = u * 256 + tid;            // 512 16B units: 128 rows x 4
        int n = e >> 2, ku = e & 3;
        cpasync16(smem_base + SM_B + n*BROW + ku*16, &g_wbf_t[(size_t)n * Hh + ku*8]);
    }
    cp_commit();

    // A resident: 128x512 f32 -> bf16, XOR-swizzled rows of 1024B
    #pragma unroll 4
    for (int u = 0; u < 64; u++) {
        int e = u * 256 + tid;            // 16384 float4 units
        int row = e >> 7, c4 = e & 127;
        float4 v = *(const float4*)&Hd[(size_t)(m0 + row) * Hh + c4*4];
        __nv_bfloat162 lo = __floats2bfloat162_rn(v.x, v.y);
        __nv_bfloat162 hi = __floats2bfloat162_rn(v.z, v.w);
        uint32_t plo = *(uint32_t*)&lo, phi = *(uint32_t*)&hi;
        uint32_t off = (uint32_t)row*1024 + (((uint32_t)c4*8) ^ (((uint32_t)(row & 7)) << 4));
        asm volatile("st.shared.v2.b32 [%0], {%1, %2};"
                     :: "r"(smem_base + off), "r"(plo), "r"(phi) : "memory");
    }

    float acc[4][4][4];
    float psum[4][2] = {};
    int qr = lane >> 2, qc = (lane & 3) * 2;

    for (int nc = 0; nc < 4; nc++) {
        #pragma unroll
        for (int mt = 0; mt < 4; mt++)
            #pragma unroll
            for (int nt = 0; nt < 4; nt++)
                #pragma unroll
                for (int c = 0; c < 4; c++) acc[mt][nt][c] = 0.f;

        for (int kc = 0; kc < 16; kc++) {
            int g = nc * 16 + kc;
            cp_wait<0>();
            __syncthreads();
            int buf = g & 1;
            if (g < 63) {
                int g1 = g + 1, nc1 = g1 >> 4, kc1 = g1 & 15;
                uint32_t dstb = smem_base + SM_B + (buf ^ 1) * BSZ;
                #pragma unroll
                for (int u = 0; u < 2; u++) {
                    int e = u * 256 + tid;
                    int n = e >> 2, ku = e & 3;
                    cpasync16(dstb + n*BROW + ku*16,
                              &g_wbf_t[(size_t)(nc1*128 + n) * Hh + kc1*32 + ku*8]);
                }
                cp_commit();
            }
            uint32_t Bst = smem_base + SM_B + buf * BSZ;
            int kcb = kc * 64;
            #pragma unroll
            for (int ks = 0; ks < 2; ks++) {
                uint32_t a[4][4], bfr[2][4];
                uint32_t colA = (uint32_t)(kcb + ks*32 + ((lane >> 4) << 4));
                #pragma unroll
                for (int mt = 0; mt < 4; mt++) {
                    uint32_t row = (uint32_t)(wm*64 + mt*16 + (lane & 15));
                    ldsm_x4(a[mt], smem_base + row*1024 + (colA ^ ((row & 7) << 4)));
                }
                #pragma unroll
                for (int bp = 0; bp < 2; bp++) {
                    uint32_t row = (uint32_t)(wn*32 + bp*16 + ((lane >> 4) << 3) + (lane & 7));
                    uint32_t colb = (uint32_t)(ks*32 + ((lane >> 3) & 1) * 16);
                    ldsm_x4(bfr[bp], Bst + row*BROW + colb);
                }
                #pragma unroll
                for (int mt = 0; mt < 4; mt++)
                    #pragma unroll
                    for (int nt = 0; nt < 4; nt++)
                        mma16816(acc[mt][nt], a[mt], &bfr[nt >> 1][(nt & 1) * 2]);
            }
        }
        // partial epilogue for this 128-col n chunk (overlaps next chunk's cp.async)
        #pragma unroll
        for (int mt = 0; mt < 4; mt++) {
            #pragma unroll
            for (int nt = 0; nt < 4; nt++) {
                int n = nc*128 + wn*32 + nt*8 + qc;
                float pb0 = __ldg(&pb[n]), pb1 = __ldg(&pb[n+1]);
                float sw0 = __ldg(&sw[n]), sw1 = __ldg(&sw[n+1]);
                __half2 h0 = __floats2half2_rn(acc[mt][nt][0] + pb0, acc[mt][nt][1] + pb1);
                uint32_t t0 = tanh2(*(uint32_t*)&h0);
                __half2 r0 = *(__half2*)&t0;
                psum[mt][0] += __low2float(r0) * sw0 + __high2float(r0) * sw1;
                __half2 h1 = __floats2half2_rn(acc[mt][nt][2] + pb0, acc[mt][nt][3] + pb1);
                uint32_t t1 = tanh2(*(uint32_t*)&h1);
                __half2 r1 = *(__half2*)&t1;
                psum[mt][1] += __low2float(r1) * sw0 + __high2float(r1) * sw1;
            }
        }
    }
    // reduce over quad (n) lanes
    #pragma unroll
    for (int mt = 0; mt < 4; mt++)
        #pragma unroll
        for (int j = 0; j < 2; j++) {
            psum[mt][j] += __shfl_xor_sync(0xffffffffu, psum[mt][j], 1);
            psum[mt][j] += __shfl_xor_sync(0xffffffffu, psum[mt][j], 2);
        }
    __syncthreads();                      // done reading A smem; reuse for reduction
    float* red = (float*)smem_raw;        // [128][4]
    if ((lane & 3) == 0) {
        #pragma unroll
        for (int mt = 0; mt < 4; mt++) {
            int m = wm*64 + mt*16 + qr;
            red[m*4 + wn]       = psum[mt][0];
            red[(m+8)*4 + wn]   = psum[mt][1];
        }
    }
    __syncthreads();
    if (tid < GM) {
        float s = red[tid*4] + red[tid*4+1] + red[tid*4+2] + red[tid*4+3];
        int c = cnt[m0 + tid]; if (c < 0) c = 0;
        g_logits[m0 + tid] = sb[0] + log1pf((float)c) + s;
    }
}

// ---------------- masked channel logits, transposed to (B,C,L) ----------------
__global__ void k_chlogits(const float* __restrict__ act) {
    __shared__ float s[64][65];
    int b  = blockIdx.x >> 6;
    int l0 = (blockIdx.x & 63) * 64;
    int tid = threadIdx.x;
    for (int idx = tid; idx < 4096; idx += 256) {
        int l = idx >> 6, c = idx & 63;
        s[l][c] = act[((size_t)(b*Ll + l0 + l)) * Cc + c];
    }
    __syncthreads();
    for (int idx = tid; idx < 4096; idx += 256) {
        int c = idx >> 6, l = idx & 63;
        float a  = s[l][c];
        float lg = g_logits[b*Ll + l0 + l];
        float v  = (a > 0.f) ? (lg + log1pf(a)) : NEGV;
        g_x[((size_t)(b*Cc + c)) * Ll + l0 + l] = v;
    }
}

// ---------------- softmax per (b,c) row ----------------
__global__ void k_softmax(float* __restrict__ wout) {
    int bc = blockIdx.x;
    const float* x = &g_x[(size_t)bc * Ll];
    float* w = &wout[(size_t)bc * Ll];
    __shared__ float red[256];
    int tid = threadIdx.x;
    float mx = NEGV;
    for (int i = tid; i < Ll; i += 256) mx = fmaxf(mx, x[i]);
    red[tid] = mx; __syncthreads();
    for (int s = 128; s; s >>= 1) { if (tid < s) red[tid] = fmaxf(red[tid], red[tid+s]); __syncthreads(); }
    mx = red[0]; __syncthreads();
    float sum = 0.f;
    for (int i = tid; i < Ll; i += 256) {
        float e = __expf(x[i] - mx);
        w[i] = e;
        sum += e;
    }
    red[tid] = sum; __syncthreads();
    for (int s = 128; s; s >>= 1) { if (tid < s) red[tid] += red[tid+s]; __syncthreads(); }
    sum = red[0];
    int any = mx > -1e8f;
    if (tid == 0) g_hasany[bc] = any;
    float inv = any ? (1.f / sum) : 0.f;
    for (int i = tid; i < Ll; i += 256) w[i] *= inv;
}

// ---------------- zero contexts ----------------
__global__ void k_zeroctx() {
    int i = blockIdx.x * 256 + threadIdx.x;
    if (i < Bb*Cc*Hh) g_ctx[i] = 0.f;
}

// ---------------- contexts ----------------
__global__ void k_ctx(const float* __restrict__ Hd, const float* __restrict__ wts) {
    __shared__ float As2[16][65];
    __shared__ float Bs2[16][64];
    int b  = blockIdx.z;
    int h0 = blockIdx.x * 64;
    int l0 = blockIdx.y * 1024;
    int tid = threadIdx.x;
    int tx = tid & 15, ty = tid >> 4;
    int arow = tid >> 2, akc = (tid & 3) * 4;
    int brow = tid >> 4, bcol = (tid & 15) * 4;
    const float* wb = wts + (size_t)b * Cc * Ll;
    const float* hb = Hd  + (size_t)b * Ll * Hh;
    float acc[4][4] = {};
    for (int k0 = 0; k0 < 1024; k0 += 16) {
        float4 av = *(const float4*)&wb[(size_t)arow * Ll + l0 + k0 + akc];
        As2[akc+0][arow] = av.x; As2[akc+1][arow] = av.y;
        As2[akc+2][arow] = av.z; As2[akc+3][arow] = av.w;
        *(float4*)&Bs2[brow][bcol] = *(const float4*)&hb[(size_t)(l0 + k0 + brow) * Hh + h0 + bcol];
        __syncthreads();
        #pragma unroll
        for (int k = 0; k < 16; k++) {
            float a[4];
            #pragma unroll
            for (int i = 0; i < 4; i++) a[i] = As2[k][ty*4+i];
            float4 b4 = *(const float4*)&Bs2[k][tx*4];
            float bv[4] = {b4.x, b4.y, b4.z, b4.w};
            #pragma unroll
            for (int i = 0; i < 4; i++)
                #pragma unroll
                for (int j = 0; j < 4; j++)
                    acc[i][j] = fmaf(a[i], bv[j], acc[i][j]);
        }
        __syncthreads();
    }
    #pragma unroll
    for (int i = 0; i < 4; i++)
        #pragma unroll
        for (int j = 0; j < 4; j++)
            atomicAdd(&g_ctx[((size_t)(b*Cc + ty*4 + i)) * Hh + h0 + tx*4 + j], acc[i][j]);
}

// ---------------- fallback for empty channels ----------------
__global__ void k_ctxfix(const float* __restrict__ Hd) {
    int i = blockIdx.x * 256 + threadIdx.x;
    if (i >= Bb*Cc*Hh) return;
    int bc = i >> 9;
    int h  = i & 511;
    if (!g_hasany[bc]) {
        int b = bc >> 6;
        g_ctx[i] = Hd[((size_t)(b*Ll + (Ll-1))) * Hh + h];
    }
}

// ---------------- final: per (b, l-tile), loop h ----------------
__global__ __launch_bounds__(256) void k_final2(const float* __restrict__ Hd,
                                                const float* __restrict__ act,
                                                const int* __restrict__ cnt,
                                                const int* __restrict__ msk,
                                                float* __restrict__ out) {
    __shared__ float s[64][65];
    __shared__ float ct[64][68];
    __shared__ float gate[64];
    __shared__ int   mk[64];
    int b  = blockIdx.y;
    int l0 = blockIdx.x * 64;
    int tid = threadIdx.x;
    for (int idx = tid; idx < 4096; idx += 256) {
        int l = idx >> 6, c = idx & 63;
        float a = act[((size_t)(b*Ll + l0 + l)) * Cc + c];
        s[l][c] = fmaxf(a, 0.f);
    }
    __syncthreads();
    if (tid < 64) {
        float sum = 0.f;
        #pragma unroll 8
        for (int c = 0; c < 64; c++) sum += s[tid][c];
        float inv = 1.f / fmaxf(sum, 1.f);
        #pragma unroll 8
        for (int c = 0; c < 64; c++) s[tid][c] *= inv;
        int gi = b*Ll + l0 + tid;
        gate[tid] = 1.f + (float)cnt[gi] / fmaxf((float)g_maxi[b], 1.f);
        mk[tid] = msk[gi];
    }
    __syncthreads();
    int tx = tid & 15, ty = tid >> 4;
    for (int h0 = 0; h0 < Hh; h0 += 64) {
        for (int idx = tid; idx < 4096; idx += 256) {
            int c = idx >> 6, h = idx & 63;
            ct[c][h] = g_ctx[((size_t)(b*Cc + c)) * Hh + h0 + h];
        }
        __syncthreads();
        float acc[4][4] = {};
        #pragma unroll 4
        for (int c = 0; c < 64; c++) {
            float a[4];
            #pragma unroll
            for (int i = 0; i < 4; i++) a[i] = s[ty*4+i][c];
            float4 b4 = *(const float4*)&ct[c][tx*4];
            float bv[4] = {b4.x, b4.y, b4.z, b4.w};
            #pragma unroll
            for (int i = 0; i < 4; i++)
                #pragma unroll
                for (int j = 0; j < 4; j++)
                    acc[i][j] = fmaf(a[i], bv[j], acc[i][j]);
        }
        #pragma unroll
        for (int i = 0; i < 4; i++) {
            int l = ty*4 + i;
            int gi = b*Ll + l0 + l;
            float g = gate[l];
            bool m = mk[l] != 0;
            #pragma unroll
            for (int j = 0; j < 4; j++) {
                size_t o = (size_t)gi * Hh + h0 + tx*4 + j;
                out[o] = m ? acc[i][j] * g : Hd[o];
            }
        }
        __syncthreads();
    }
}

// ---------------- launch ----------------
extern "C" void kernel_launch(void* const* d_in, const int* in_sizes, int n_in,
                              void* d_out, int out_size) {
    const float* hidden = (const float*)d_in[0];
    const int*   mask   = (const int*)d_in[1];
    const int*   cnt    = (const int*)d_in[2];
    const float* act    = (const float*)d_in[3];
    const float* pw     = (const float*)d_in[4];
    const float* pb     = (const float*)d_in[5];
    const float* sw     = (const float*)d_in[6];
    const float* sb     = (const float*)d_in[7];
    float* out  = (float*)d_out;
    float* wout = out + OUT_ATT;

    static bool attr_done = false;
    if (!attr_done) {
        cudaFuncSetAttribute(k_gemm1_v3, cudaFuncAttributeMaxDynamicSharedMemorySize, GEMM_SMEM);
        attr_done = true;
    }

    k_cvt_wT<<<dim3(Aa/32, Aa/32), dim3(32,32)>>>(pw);
    k_maxcount<<<Bb*8, 512>>>(cnt);
    k_gemm1_v3<<<BL/GM, 256, GEMM_SMEM>>>(hidden, pb, sw, cnt, sb);
    k_chlogits<<<Bb*(Ll/64), 256>>>(act);
    k_softmax<<<Bb*Cc, 256>>>(wout);
    k_zeroctx<<<(Bb*Cc*Hh+255)/256, 256>>>();
    k_ctx<<<dim3(Hh/64, Ll/1024, Bb), 256>>>(hidden, wout);
    k_ctxfix<<<(Bb*Cc*Hh+255)/256, 256>>>(hidden);
    k_final2<<<dim3(Ll/64, Bb), 256>>>(hidden, act, cnt, mask, out);
}

// round 7
// speedup vs baseline: 2.7756x; 1.2227x over previous
#include <cuda_runtime.h>
#include <cuda_bf16.h>
#include <cuda_fp16.h>
#include <cstdint>

#define Bb 8
#define Ll 4096
#define Hh 512
#define Cc 64
#define Aa 512
#define BL (Bb*Ll)
#define NEGV (-1000000000.0f)
#define OUT_ATT ((size_t)BL*Hh)

// ---- GEMM1 config ----
#define GM 128
#define ABYTES (128*1024)
#define BROW 80
#define BSZ (128*BROW)
#define SM_B ABYTES
#define GEMM_SMEM (ABYTES + 2*BSZ)

// ---------------- scratch ----------------
__device__ float g_logits[BL];
__device__ float g_x[(size_t)Bb*Cc*Ll];
__device__ float g_ctx[(size_t)Bb*Cc*Hh];
__device__ int   g_hasany[Bb*Cc];
__device__ int   g_maxi[Bb];
__device__ __nv_bfloat16 g_wbf_t[(size_t)Aa*Hh];

// ---------------- helpers ----------------
__device__ __forceinline__ uint32_t smem_u32(const void* p) {
    uint32_t a;
    asm("{ .reg .u64 t; cvta.to.shared.u64 t, %1; cvt.u32.u64 %0, t; }" : "=r"(a) : "l"(p));
    return a;
}
__device__ __forceinline__ void cpasync16(uint32_t dst, const void* src) {
    asm volatile("cp.async.cg.shared.global [%0], [%1], 16;" :: "r"(dst), "l"(src));
}
__device__ __forceinline__ void cp_commit() { asm volatile("cp.async.commit_group;"); }
template<int N> __device__ __forceinline__ void cp_wait() {
    asm volatile("cp.async.wait_group %0;" :: "n"(N));
}
__device__ __forceinline__ void ldsm_x4(uint32_t* r, uint32_t addr) {
    asm volatile("ldmatrix.sync.aligned.m8n8.x4.shared.b16 {%0,%1,%2,%3}, [%4];"
        : "=r"(r[0]), "=r"(r[1]), "=r"(r[2]), "=r"(r[3]) : "r"(addr));
}
__device__ __forceinline__ void mma16816(float* c, const uint32_t* a, const uint32_t* b) {
    asm volatile(
        "mma.sync.aligned.m16n8k16.row.col.f32.bf16.bf16.f32 "
        "{%0,%1,%2,%3}, {%4,%5,%6,%7}, {%8,%9}, {%0,%1,%2,%3};"
        : "+f"(c[0]), "+f"(c[1]), "+f"(c[2]), "+f"(c[3])
        : "r"(a[0]), "r"(a[1]), "r"(a[2]), "r"(a[3]), "r"(b[0]), "r"(b[1]));
}
__device__ __forceinline__ void mma_tf32(float* c, const uint32_t* a, const uint32_t* b) {
    asm volatile(
        "mma.sync.aligned.m16n8k8.row.col.f32.tf32.tf32.f32 "
        "{%0,%1,%2,%3}, {%4,%5,%6,%7}, {%8,%9}, {%0,%1,%2,%3};"
        : "+f"(c[0]), "+f"(c[1]), "+f"(c[2]), "+f"(c[3])
        : "r"(a[0]), "r"(a[1]), "r"(a[2]), "r"(a[3]), "r"(b[0]), "r"(b[1]));
}
__device__ __forceinline__ uint32_t f2tf32(float x) {
    uint32_t r;
    asm("cvt.rna.tf32.f32 %0, %1;" : "=r"(r) : "f"(x));
    return r;
}
__device__ __forceinline__ uint32_t tanh2(uint32_t x) {
    uint32_t r;
    asm("tanh.approx.f16x2 %0, %1;" : "=r"(r) : "r"(x));
    return r;
}

// ---------------- transpose + convert W ----------------
__global__ void k_cvt_wT(const float* __restrict__ W) {
    __shared__ float tile[32][33];
    int tx = threadIdx.x, ty = threadIdx.y;
    int k = blockIdx.x * 32 + ty;
    int n = blockIdx.y * 32 + tx;
    tile[ty][tx] = W[(size_t)k * Aa + n];
    __syncthreads();
    int no = blockIdx.y * 32 + ty;
    int ko = blockIdx.x * 32 + tx;
    g_wbf_t[(size_t)no * Hh + ko] = __float2bfloat16(tile[tx][ty]);
}

// ---------------- per-batch max count ----------------
__global__ void k_maxcount(const int* __restrict__ cnt) {
    int b = blockIdx.x >> 3, seg = blockIdx.x & 7;
    int v = cnt[b*Ll + seg*512 + threadIdx.x];
    #pragma unroll
    for (int o = 16; o; o >>= 1) v = max(v, __shfl_xor_sync(0xffffffffu, v, o));
    if ((threadIdx.x & 31) == 0) atomicMax(&g_maxi[b], v);
}

// ---------------- GEMM1 v3 (unchanged from R6) ----------------
extern __shared__ char smem_raw[];

__global__ __launch_bounds__(256)
void k_gemm1_v3(const float* __restrict__ Hd,
                const float* __restrict__ pb, const float* __restrict__ sw,
                const int* __restrict__ cnt, const float* __restrict__ sb) {
    uint32_t smem_base = smem_u32(smem_raw);
    int tid = threadIdx.x, lane = tid & 31, wid = tid >> 5;
    int wm = wid >> 2, wn = wid & 3;
    int m0 = blockIdx.x * GM;

    #pragma unroll
    for (int u = 0; u < 2; u++) {
        int e = u * 256 + tid;
        int n = e >> 2, ku = e & 3;
        cpasync16(smem_base + SM_B + n*BROW + ku*16, &g_wbf_t[(size_t)n * Hh + ku*8]);
    }
    cp_commit();

    #pragma unroll 4
    for (int u = 0; u < 64; u++) {
        int e = u * 256 + tid;
        int row = e >> 7, c4 = e & 127;
        float4 v = *(const float4*)&Hd[(size_t)(m0 + row) * Hh + c4*4];
        __nv_bfloat162 lo = __floats2bfloat162_rn(v.x, v.y);
        __nv_bfloat162 hi = __floats2bfloat162_rn(v.z, v.w);
        uint32_t plo = *(uint32_t*)&lo, phi = *(uint32_t*)&hi;
        uint32_t off = (uint32_t)row*1024 + (((uint32_t)c4*8) ^ (((uint32_t)(row & 7)) << 4));
        asm volatile("st.shared.v2.b32 [%0], {%1, %2};"
                     :: "r"(smem_base + off), "r"(plo), "r"(phi) : "memory");
    }

    float acc[4][4][4];
    float psum[4][2] = {};
    int qr = lane >> 2, qc = (lane & 3) * 2;

    for (int nc = 0; nc < 4; nc++) {
        #pragma unroll
        for (int mt = 0; mt < 4; mt++)
            #pragma unroll
            for (int nt = 0; nt < 4; nt++)
                #pragma unroll
                for (int c = 0; c < 4; c++) acc[mt][nt][c] = 0.f;

        for (int kc = 0; kc < 16; kc++) {
            int g = nc * 16 + kc;
            cp_wait<0>();
            __syncthreads();
            int buf = g & 1;
            if (g < 63) {
                int g1 = g + 1, nc1 = g1 >> 4, kc1 = g1 & 15;
                uint32_t dstb = smem_base + SM_B + (buf ^ 1) * BSZ;
                #pragma unroll
                for (int u = 0; u < 2; u++) {
                    int e = u * 256 + tid;
                    int n = e >> 2, ku = e & 3;
                    cpasync16(dstb + n*BROW + ku*16,
                              &g_wbf_t[(size_t)(nc1*128 + n) * Hh + kc1*32 + ku*8]);
                }
                cp_commit();
            }
            uint32_t Bst = smem_base + SM_B + buf * BSZ;
            int kcb = kc * 64;
            #pragma unroll
            for (int ks = 0; ks < 2; ks++) {
                uint32_t a[4][4], bfr[2][4];
                uint32_t colA = (uint32_t)(kcb + ks*32 + ((lane >> 4) << 4));
                #pragma unroll
                for (int mt = 0; mt < 4; mt++) {
                    uint32_t row = (uint32_t)(wm*64 + mt*16 + (lane & 15));
                    ldsm_x4(a[mt], smem_base + row*1024 + (colA ^ ((row & 7) << 4)));
                }
                #pragma unroll
                for (int bp = 0; bp < 2; bp++) {
                    uint32_t row = (uint32_t)(wn*32 + bp*16 + ((lane >> 4) << 3) + (lane & 7));
                    uint32_t colb = (uint32_t)(ks*32 + ((lane >> 3) & 1) * 16);
                    ldsm_x4(bfr[bp], Bst + row*BROW + colb);
                }
                #pragma unroll
                for (int mt = 0; mt < 4; mt++)
                    #pragma unroll
                    for (int nt = 0; nt < 4; nt++)
                        mma16816(acc[mt][nt], a[mt], &bfr[nt >> 1][(nt & 1) * 2]);
            }
        }
        #pragma unroll
        for (int mt = 0; mt < 4; mt++) {
            #pragma unroll
            for (int nt = 0; nt < 4; nt++) {
                int n = nc*128 + wn*32 + nt*8 + qc;
                float pb0 = __ldg(&pb[n]), pb1 = __ldg(&pb[n+1]);
                float sw0 = __ldg(&sw[n]), sw1 = __ldg(&sw[n+1]);
                __half2 h0 = __floats2half2_rn(acc[mt][nt][0] + pb0, acc[mt][nt][1] + pb1);
                uint32_t t0 = tanh2(*(uint32_t*)&h0);
                __half2 r0 = *(__half2*)&t0;
                psum[mt][0] += __low2float(r0) * sw0 + __high2float(r0) * sw1;
                __half2 h1 = __floats2half2_rn(acc[mt][nt][2] + pb0, acc[mt][nt][3] + pb1);
                uint32_t t1 = tanh2(*(uint32_t*)&h1);
                __half2 r1 = *(__half2*)&t1;
                psum[mt][1] += __low2float(r1) * sw0 + __high2float(r1) * sw1;
            }
        }
    }
    #pragma unroll
    for (int mt = 0; mt < 4; mt++)
        #pragma unroll
        for (int j = 0; j < 2; j++) {
            psum[mt][j] += __shfl_xor_sync(0xffffffffu, psum[mt][j], 1);
            psum[mt][j] += __shfl_xor_sync(0xffffffffu, psum[mt][j], 2);
        }
    __syncthreads();
    float* red = (float*)smem_raw;
    if ((lane & 3) == 0) {
        #pragma unroll
        for (int mt = 0; mt < 4; mt++) {
            int m = wm*64 + mt*16 + qr;
            red[m*4 + wn]     = psum[mt][0];
            red[(m+8)*4 + wn] = psum[mt][1];
        }
    }
    __syncthreads();
    if (tid < GM) {
        float s = red[tid*4] + red[tid*4+1] + red[tid*4+2] + red[tid*4+3];
        int c = cnt[m0 + tid]; if (c < 0) c = 0;
        g_logits[m0 + tid] = sb[0] + log1pf((float)c) + s;
    }
}

// ---------------- masked channel logits ----------------
__global__ void k_chlogits(const float* __restrict__ act) {
    __shared__ float s[64][65];
    int b  = blockIdx.x >> 6;
    int l0 = (blockIdx.x & 63) * 64;
    int tid = threadIdx.x;
    for (int idx = tid; idx < 4096; idx += 256) {
        int l = idx >> 6, c = idx & 63;
        s[l][c] = act[((size_t)(b*Ll + l0 + l)) * Cc + c];
    }
    __syncthreads();
    for (int idx = tid; idx < 4096; idx += 256) {
        int c = idx >> 6, l = idx & 63;
        float a  = s[l][c];
        float lg = g_logits[b*Ll + l0 + l];
        float v  = (a > 0.f) ? (lg + log1pf(a)) : NEGV;
        g_x[((size_t)(b*Cc + c)) * Ll + l0 + l] = v;
    }
}

// ---------------- softmax per (b,c) row ----------------
__global__ void k_softmax(float* __restrict__ wout) {
    int bc = blockIdx.x;
    const float* x = &g_x[(size_t)bc * Ll];
    float* w = &wout[(size_t)bc * Ll];
    __shared__ float red[256];
    int tid = threadIdx.x;
    float mx = NEGV;
    for (int i = tid; i < Ll; i += 256) mx = fmaxf(mx, x[i]);
    red[tid] = mx; __syncthreads();
    for (int s = 128; s; s >>= 1) { if (tid < s) red[tid] = fmaxf(red[tid], red[tid+s]); __syncthreads(); }
    mx = red[0]; __syncthreads();
    float sum = 0.f;
    for (int i = tid; i < Ll; i += 256) {
        float e = __expf(x[i] - mx);
        w[i] = e;
        sum += e;
    }
    red[tid] = sum; __syncthreads();
    for (int s = 128; s; s >>= 1) { if (tid < s) red[tid] += red[tid+s]; __syncthreads(); }
    sum = red[0];
    int any = mx > -1e8f;
    if (tid == 0) g_hasany[bc] = any;
    float inv = any ? (1.f / sum) : 0.f;
    for (int i = tid; i < Ll; i += 256) w[i] *= inv;
}

// ---------------- zero contexts ----------------
__global__ void k_zeroctx() {
    int i = blockIdx.x * 256 + threadIdx.x;
    if (i < Bb*Cc*Hh) g_ctx[i] = 0.f;
}

// ---------------- contexts via tf32 tensor cores ----------------
// grid (h-tile 8, l-chunk 4, b 8); block 256 = 8 warps (2m x 4n)
// M=64 (C), N=64 (h tile), K=1024 (l chunk), k-slab 32, double buffered
#define CTX_AP 36
#define CTX_BP 72
__global__ __launch_bounds__(256) void k_ctx_tf32(const float* __restrict__ Hd,
                                                  const float* __restrict__ wts) {
    __shared__ float As[2][64*CTX_AP];
    __shared__ float Bs[2][32*CTX_BP];
    int b  = blockIdx.z;
    int h0 = blockIdx.x * 64;
    int l0 = blockIdx.y * 1024;
    int tid = threadIdx.x, lane = tid & 31, wid = tid >> 5;
    int wm = wid >> 2, wn = wid & 3;       // warp tile 32m x 16n
    int g = lane >> 2, tq = lane & 3;
    const float* wb = wts + (size_t)b * Cc * Ll;
    const float* hb = Hd  + (size_t)b * Ll * Hh;

    uint32_t sA0 = smem_u32(&As[0][0]), sA1 = smem_u32(&As[1][0]);
    uint32_t sB0 = smem_u32(&Bs[0][0]), sB1 = smem_u32(&Bs[1][0]);

    // prefetch slab 0
    {
        #pragma unroll
        for (int u = 0; u < 2; u++) {
            int e = u*256 + tid;               // A: 512 float4 units (64 x 8)
            int c = e >> 3, kq = e & 7;
            cpasync16(sA0 + (c*CTX_AP + kq*4)*4, &wb[(size_t)c * Ll + l0 + kq*4]);
        }
        #pragma unroll
        for (int u = 0; u < 2; u++) {
            int e = u*256 + tid;               // B: 512 float4 units (32 x 16)
            int kk = e >> 4, nq = e & 15;
            cpasync16(sB0 + (kk*CTX_BP + nq*4)*4, &hb[(size_t)(l0 + kk) * Hh + h0 + nq*4]);
        }
        cp_commit();
    }

    float acc[2][2][4] = {};
    for (int s = 0; s < 32; s++) {
        cp_wait<0>();
        __syncthreads();
        int buf = s & 1;
        if (s < 31) {
            int k0 = l0 + (s + 1) * 32;
            uint32_t dA = (buf ? sA0 : sA1), dB = (buf ? sB0 : sB1);
            #pragma unroll
            for (int u = 0; u < 2; u++) {
                int e = u*256 + tid;
                int c = e >> 3, kq = e & 7;
                cpasync16(dA + (c*CTX_AP + kq*4)*4, &wb[(size_t)c * Ll + k0 + kq*4]);
            }
            #pragma unroll
            for (int u = 0; u < 2; u++) {
                int e = u*256 + tid;
                int kk = e >> 4, nq = e & 15;
                cpasync16(dB + (kk*CTX_BP + nq*4)*4, &hb[(size_t)(k0 + kk) * Hh + h0 + nq*4]);
            }
            cp_commit();
        }
        const float* Ab = As[buf];
        const float* Bbuf = Bs[buf];
        #pragma unroll
        for (int ks = 0; ks < 4; ks++) {
            int kb = ks * 8;
            uint32_t af[2][4], bf[2][2];
            #pragma unroll
            for (int mt = 0; mt < 2; mt++) {
                int m = wm*32 + mt*16;
                af[mt][0] = f2tf32(Ab[(m + g    )*CTX_AP + kb + tq    ]);
                af[mt][1] = f2tf32(Ab[(m + g + 8)*CTX_AP + kb + tq    ]);
                af[mt][2] = f2tf32(Ab[(m + g    )*CTX_AP + kb + tq + 4]);
                af[mt][3] = f2tf32(Ab[(m + g + 8)*CTX_AP + kb + tq + 4]);
            }
            #pragma unroll
            for (int nt = 0; nt < 2; nt++) {
                int n = wn*16 + nt*8;
                bf[nt][0] = f2tf32(Bbuf[(kb + tq    )*CTX_BP + n + g]);
                bf[nt][1] = f2tf32(Bbuf[(kb + tq + 4)*CTX_BP + n + g]);
            }
            #pragma unroll
            for (int mt = 0; mt < 2; mt++)
                #pragma unroll
                for (int nt = 0; nt < 2; nt++)
                    mma_tf32(acc[mt][nt], af[mt], bf[nt]);
        }
    }
    #pragma unroll
    for (int mt = 0; mt < 2; mt++)
        #pragma unroll
        for (int nt = 0; nt < 2; nt++) {
            int m = wm*32 + mt*16 + g;
            int n = h0 + wn*16 + nt*8 + tq*2;
            float* base0 = &g_ctx[((size_t)(b*Cc + m)) * Hh + n];
            atomicAdd(base0,     acc[mt][nt][0]);
            atomicAdd(base0 + 1, acc[mt][nt][1]);
            float* base1 = &g_ctx[((size_t)(b*Cc + m + 8)) * Hh + n];
            atomicAdd(base1,     acc[mt][nt][2]);
            atomicAdd(base1 + 1, acc[mt][nt][3]);
        }
}

// ---------------- fallback for empty channels ----------------
__global__ void k_ctxfix(const float* __restrict__ Hd) {
    int i = blockIdx.x * 256 + threadIdx.x;
    if (i >= Bb*Cc*Hh) return;
    int bc = i >> 9;
    int h  = i & 511;
    if (!g_hasany[bc]) {
        int b = bc >> 6;
        g_ctx[i] = Hd[((size_t)(b*Ll + (Ll-1))) * Hh + h];
    }
}

// ---------------- final: per (b, l-tile), loop h ----------------
__global__ __launch_bounds__(256) void k_final2(const float* __restrict__ Hd,
                                                const float* __restrict__ act,
                                                const int* __restrict__ cnt,
                                                const int* __restrict__ msk,
                                                float* __restrict__ out) {
    __shared__ float s[64][65];
    __shared__ float ct[64][68];
    __shared__ float gate[64];
    __shared__ int   mk[64];
    int b  = blockIdx.y;
    int l0 = blockIdx.x * 64;
    int tid = threadIdx.x;
    for (int idx = tid; idx < 4096; idx += 256) {
        int l = idx >> 6, c = idx & 63;
        float a = act[((size_t)(b*Ll + l0 + l)) * Cc + c];
        s[l][c] = fmaxf(a, 0.f);
    }
    __syncthreads();
    if (tid < 64) {
        float sum = 0.f;
        #pragma unroll 8
        for (int c = 0; c < 64; c++) sum += s[tid][c];
        float inv = 1.f / fmaxf(sum, 1.f);
        #pragma unroll 8
        for (int c = 0; c < 64; c++) s[tid][c] *= inv;
        int gi = b*Ll + l0 + tid;
        gate[tid] = 1.f + (float)cnt[gi] / fmaxf((float)g_maxi[b], 1.f);
        mk[tid] = msk[gi];
    }
    __syncthreads();
    int tx = tid & 15, ty = tid >> 4;
    for (int h0 = 0; h0 < Hh; h0 += 64) {
        for (int idx = tid; idx < 4096; idx += 256) {
            int c = idx >> 6, h = idx & 63;
            ct[c][h] = g_ctx[((size_t)(b*Cc + c)) * Hh + h0 + h];
        }
        __syncthreads();
        float acc[4][4] = {};
        #pragma unroll 4
        for (int c = 0; c < 64; c++) {
            float a[4];
            #pragma unroll
            for (int i = 0; i < 4; i++) a[i] = s[ty*4+i][c];
            float4 b4 = *(const float4*)&ct[c][tx*4];
            float bv[4] = {b4.x, b4.y, b4.z, b4.w};
            #pragma unroll
            for (int i = 0; i < 4; i++)
                #pragma unroll
                for (int j = 0; j < 4; j++)
                    acc[i][j] = fmaf(a[i], bv[j], acc[i][j]);
        }
        #pragma unroll
        for (int i = 0; i < 4; i++) {
            int l = ty*4 + i;
            int gi = b*Ll + l0 + l;
            float g = gate[l];
            bool m = mk[l] != 0;
            #pragma unroll
            for (int j = 0; j < 4; j++) {
                size_t o = (size_t)gi * Hh + h0 + tx*4 + j;
                out[o] = m ? acc[i][j] * g : Hd[o];
            }
        }
        __syncthreads();
    }
}

// ---------------- launch ----------------
extern "C" void kernel_launch(void* const* d_in, const int* in_sizes, int n_in,
                              void* d_out, int out_size) {
    const float* hidden = (const float*)d_in[0];
    const int*   mask   = (const int*)d_in[1];
    const int*   cnt    = (const int*)d_in[2];
    const float* act    = (const float*)d_in[3];
    const float* pw     = (const float*)d_in[4];
    const float* pb     = (const float*)d_in[5];
    const float* sw     = (const float*)d_in[6];
    const float* sb     = (const float*)d_in[7];
    float* out  = (float*)d_out;
    float* wout = out + OUT_ATT;

    static bool attr_done = false;
    if (!attr_done) {
        cudaFuncSetAttribute(k_gemm1_v3, cudaFuncAttributeMaxDynamicSharedMemorySize, GEMM_SMEM);
        attr_done = true;
    }

    k_cvt_wT<<<dim3(Aa/32, Aa/32), dim3(32,32)>>>(pw);
    k_maxcount<<<Bb*8, 512>>>(cnt);
    k_gemm1_v3<<<BL/GM, 256, GEMM_SMEM>>>(hidden, pb, sw, cnt, sb);
    k_chlogits<<<Bb*(Ll/64), 256>>>(act);
    k_softmax<<<Bb*Cc, 256>>>(wout);
    k_zeroctx<<<(Bb*Cc*Hh+255)/256, 256>>>();
    k_ctx_tf32<<<dim3(Hh/64, Ll/1024, Bb), 256>>>(hidden, wout);
    k_ctxfix<<<(Bb*Cc*Hh+255)/256, 256>>>(hidden);
    k_final2<<<dim3(Ll/64, Bb), 256>>>(hidden, act, cnt, mask, out);
}

// round 9
// speedup vs baseline: 3.1399x; 1.1312x over previous
#include <cuda_runtime.h>
#include <cuda_bf16.h>
#include <cuda_fp16.h>
#include <cstdint>

#define Bb 8
#define Ll 4096
#define Hh 512
#define Cc 64
#define Aa 512
#define BL (Bb*Ll)
#define NEGV (-1000000000.0f)
#define OUT_ATT ((size_t)BL*Hh)

// ---- GEMM1 config: GM=64, A resident, 2 CTAs/SM ----
#define GM 64
#define ABYTES (GM*1024)           // 64 rows x 512 bf16 = 65536
#define BROW 80
#define BSZ (128*BROW)             // 10240
#define SM_B ABYTES
#define GEMM_SMEM (ABYTES + 2*BSZ) // 86016

// ---------------- scratch ----------------
__device__ float g_logits[BL];
__device__ float g_x[(size_t)Bb*Cc*Ll];
__device__ float g_ctx[(size_t)Bb*Cc*Hh];
__device__ int   g_hasany[Bb*Cc];
__device__ int   g_maxi[Bb];
__device__ __nv_bfloat16 g_wbf_t[(size_t)Aa*Hh];

// ---------------- helpers ----------------
__device__ __forceinline__ uint32_t smem_u32(const void* p) {
    uint32_t a;
    asm("{ .reg .u64 t; cvta.to.shared.u64 t, %1; cvt.u32.u64 %0, t; }" : "=r"(a) : "l"(p));
    return a;
}
__device__ __forceinline__ void cpasync16(uint32_t dst, const void* src) {
    asm volatile("cp.async.cg.shared.global [%0], [%1], 16;" :: "r"(dst), "l"(src));
}
__device__ __forceinline__ void cp_commit() { asm volatile("cp.async.commit_group;"); }
template<int N> __device__ __forceinline__ void cp_wait() {
    asm volatile("cp.async.wait_group %0;" :: "n"(N));
}
__device__ __forceinline__ void ldsm_x4(uint32_t* r, uint32_t addr) {
    asm volatile("ldmatrix.sync.aligned.m8n8.x4.shared.b16 {%0,%1,%2,%3}, [%4];"
        : "=r"(r[0]), "=r"(r[1]), "=r"(r[2]), "=r"(r[3]) : "r"(addr));
}
__device__ __forceinline__ void mma16816(float* c, const uint32_t* a, const uint32_t* b) {
    asm volatile(
        "mma.sync.aligned.m16n8k16.row.col.f32.bf16.bf16.f32 "
        "{%0,%1,%2,%3}, {%4,%5,%6,%7}, {%8,%9}, {%0,%1,%2,%3};"
        : "+f"(c[0]), "+f"(c[1]), "+f"(c[2]), "+f"(c[3])
        : "r"(a[0]), "r"(a[1]), "r"(a[2]), "r"(a[3]), "r"(b[0]), "r"(b[1]));
}
__device__ __forceinline__ void mma_tf32(float* c, const uint32_t* a, const uint32_t* b) {
    asm volatile(
        "mma.sync.aligned.m16n8k8.row.col.f32.tf32.tf32.f32 "
        "{%0,%1,%2,%3}, {%4,%5,%6,%7}, {%8,%9}, {%0,%1,%2,%3};"
        : "+f"(c[0]), "+f"(c[1]), "+f"(c[2]), "+f"(c[3])
        : "r"(a[0]), "r"(a[1]), "r"(a[2]), "r"(a[3]), "r"(b[0]), "r"(b[1]));
}
__device__ __forceinline__ uint32_t f2tf32(float x) {
    uint32_t r;
    asm("cvt.rna.tf32.f32 %0, %1;" : "=r"(r) : "f"(x));
    return r;
}
__device__ __forceinline__ uint32_t tanh2(uint32_t x) {
    uint32_t r;
    asm("tanh.approx.f16x2 %0, %1;" : "=r"(r) : "r"(x));
    return r;
}

// ---------------- transpose + convert W ----------------
__global__ void k_cvt_wT(const float* __restrict__ W) {
    __shared__ float tile[32][33];
    int tx = threadIdx.x, ty = threadIdx.y;
    int k = blockIdx.x * 32 + ty;
    int n = blockIdx.y * 32 + tx;
    tile[ty][tx] = W[(size_t)k * Aa + n];
    __syncthreads();
    int no = blockIdx.y * 32 + ty;
    int ko = blockIdx.x * 32 + tx;
    g_wbf_t[(size_t)no * Hh + ko] = __float2bfloat16(tile[tx][ty]);
}

// ---------------- per-batch max count ----------------
__global__ void k_maxcount(const int* __restrict__ cnt) {
    int b = blockIdx.x >> 3, seg = blockIdx.x & 7;
    int v = cnt[b*Ll + seg*512 + threadIdx.x];
    #pragma unroll
    for (int o = 16; o; o >>= 1) v = max(v, __shfl_xor_sync(0xffffffffu, v, o));
    if ((threadIdx.x & 31) == 0) atomicMax(&g_maxi[b], v);
}

// ---------------- GEMM1 v4: GM=64, 2 CTA/SM ----------------
extern __shared__ char smem_raw[];

__global__ __launch_bounds__(256)
void k_gemm1_v4(const float* __restrict__ Hd,
                const float* __restrict__ pb, const float* __restrict__ sw,
                const int* __restrict__ cnt, const float* __restrict__ sb) {
    uint32_t smem_base = smem_u32(smem_raw);
    int tid = threadIdx.x, lane = tid & 31, wid = tid >> 5;
    int wm = wid >> 2, wn = wid & 3;      // 2m x 4n warps; warp tile 32m x 32n
    int m0 = blockIdx.x * GM;

    // prefetch B chunk 0
    #pragma unroll
    for (int u = 0; u < 2; u++) {
        int e = u * 256 + tid;
        int n = e >> 2, ku = e & 3;
        cpasync16(smem_base + SM_B + n*BROW + ku*16, &g_wbf_t[(size_t)n * Hh + ku*8]);
    }
    cp_commit();

    // A resident: 64x512 f32 -> bf16, XOR-swizzled rows of 1024B
    #pragma unroll 4
    for (int u = 0; u < 32; u++) {
        int e = u * 256 + tid;            // 8192 float4 units
        int row = e >> 7, c4 = e & 127;
        float4 v = *(const float4*)&Hd[(size_t)(m0 + row) * Hh + c4*4];
        __nv_bfloat162 lo = __floats2bfloat162_rn(v.x, v.y);
        __nv_bfloat162 hi = __floats2bfloat162_rn(v.z, v.w);
        uint32_t plo = *(uint32_t*)&lo, phi = *(uint32_t*)&hi;
        uint32_t off = (uint32_t)row*1024 + (((uint32_t)c4*8) ^ (((uint32_t)(row & 7)) << 4));
        asm volatile("st.shared.v2.b32 [%0], {%1, %2};"
                     :: "r"(smem_base + off), "r"(plo), "r"(phi) : "memory");
    }

    float acc[2][4][4];
    float psum[2][2] = {};
    int qr = lane >> 2, qc = (lane & 3) * 2;

    for (int nc = 0; nc < 4; nc++) {
        #pragma unroll
        for (int mt = 0; mt < 2; mt++)
            #pragma unroll
            for (int nt = 0; nt < 4; nt++)
                #pragma unroll
                for (int c = 0; c < 4; c++) acc[mt][nt][c] = 0.f;

        for (int kc = 0; kc < 16; kc++) {
            int g = nc * 16 + kc;
            cp_wait<0>();
            __syncthreads();
            int buf = g & 1;
            if (g < 63) {
                int g1 = g + 1, nc1 = g1 >> 4, kc1 = g1 & 15;
                uint32_t dstb = smem_base + SM_B + (buf ^ 1) * BSZ;
                #pragma unroll
                for (int u = 0; u < 2; u++) {
                    int e = u * 256 + tid;
                    int n = e >> 2, ku = e & 3;
                    cpasync16(dstb + n*BROW + ku*16,
                              &g_wbf_t[(size_t)(nc1*128 + n) * Hh + kc1*32 + ku*8]);
                }
                cp_commit();
            }
            uint32_t Bst = smem_base + SM_B + buf * BSZ;
            int kcb = kc * 64;
            #pragma unroll
            for (int ks = 0; ks < 2; ks++) {
                uint32_t a[2][4], bfr[2][4];
                uint32_t colA = (uint32_t)(kcb + ks*32 + ((lane >> 4) << 4));
                #pragma unroll
                for (int mt = 0; mt < 2; mt++) {
                    uint32_t row = (uint32_t)(wm*32 + mt*16 + (lane & 15));
                    ldsm_x4(a[mt], smem_base + row*1024 + (colA ^ ((row & 7) << 4)));
                }
                #pragma unroll
                for (int bp = 0; bp < 2; bp++) {
                    uint32_t row = (uint32_t)(wn*32 + bp*16 + ((lane >> 4) << 3) + (lane & 7));
                    uint32_t colb = (uint32_t)(ks*32 + ((lane >> 3) & 1) * 16);
                    ldsm_x4(bfr[bp], Bst + row*BROW + colb);
                }
                #pragma unroll
                for (int mt = 0; mt < 2; mt++)
                    #pragma unroll
                    for (int nt = 0; nt < 4; nt++)
                        mma16816(acc[mt][nt], a[mt], &bfr[nt >> 1][(nt & 1) * 2]);
            }
        }
        // partial epilogue (overlaps next chunk's cp.async)
        #pragma unroll
        for (int mt = 0; mt < 2; mt++) {
            #pragma unroll
            for (int nt = 0; nt < 4; nt++) {
                int n = nc*128 + wn*32 + nt*8 + qc;
                float pb0 = __ldg(&pb[n]), pb1 = __ldg(&pb[n+1]);
                float sw0 = __ldg(&sw[n]), sw1 = __ldg(&sw[n+1]);
                __half2 h0 = __floats2half2_rn(acc[mt][nt][0] + pb0, acc[mt][nt][1] + pb1);
                uint32_t t0 = tanh2(*(uint32_t*)&h0);
                __half2 r0 = *(__half2*)&t0;
                psum[mt][0] += __low2float(r0) * sw0 + __high2float(r0) * sw1;
                __half2 h1 = __floats2half2_rn(acc[mt][nt][2] + pb0, acc[mt][nt][3] + pb1);
                uint32_t t1 = tanh2(*(uint32_t*)&h1);
                __half2 r1 = *(__half2*)&t1;
                psum[mt][1] += __low2float(r1) * sw0 + __high2float(r1) * sw1;
            }
        }
    }
    #pragma unroll
    for (int mt = 0; mt < 2; mt++)
        #pragma unroll
        for (int j = 0; j < 2; j++) {
            psum[mt][j] += __shfl_xor_sync(0xffffffffu, psum[mt][j], 1);
            psum[mt][j] += __shfl_xor_sync(0xffffffffu, psum[mt][j], 2);
        }
    __syncthreads();
    float* red = (float*)smem_raw;        // [64][4]
    if ((lane & 3) == 0) {
        #pragma unroll
        for (int mt = 0; mt < 2; mt++) {
            int m = wm*32 + mt*16 + qr;
            red[m*4 + wn]     = psum[mt][0];
            red[(m+8)*4 + wn] = psum[mt][1];
        }
    }
    __syncthreads();
    if (tid < GM) {
        float s = red[tid*4] + red[tid*4+1] + red[tid*4+2] + red[tid*4+3];
        int c = cnt[m0 + tid]; if (c < 0) c = 0;
        g_logits[m0 + tid] = sb[0] + log1pf((float)c) + s;
    }
}

// ---------------- masked channel logits ----------------
__global__ void k_chlogits(const float* __restrict__ act) {
    __shared__ float s[64][65];
    int b  = blockIdx.x >> 6;
    int l0 = (blockIdx.x & 63) * 64;
    int tid = threadIdx.x;
    for (int idx = tid; idx < 4096; idx += 256) {
        int l = idx >> 6, c = idx & 63;
        s[l][c] = act[((size_t)(b*Ll + l0 + l)) * Cc + c];
    }
    __syncthreads();
    for (int idx = tid; idx < 4096; idx += 256) {
        int c = idx >> 6, l = idx & 63;
        float a  = s[l][c];
        float lg = g_logits[b*Ll + l0 + l];
        float v  = (a > 0.f) ? (lg + log1pf(a)) : NEGV;
        g_x[((size_t)(b*Cc + c)) * Ll + l0 + l] = v;
    }
}

// ---------------- softmax per (b,c) row ----------------
__global__ void k_softmax(float* __restrict__ wout) {
    int bc = blockIdx.x;
    const float* x = &g_x[(size_t)bc * Ll];
    float* w = &wout[(size_t)bc * Ll];
    __shared__ float red[256];
    int tid = threadIdx.x;
    float mx = NEGV;
    for (int i = tid; i < Ll; i += 256) mx = fmaxf(mx, x[i]);
    red[tid] = mx; __syncthreads();
    for (int s = 128; s; s >>= 1) { if (tid < s) red[tid] = fmaxf(red[tid], red[tid+s]); __syncthreads(); }
    mx = red[0]; __syncthreads();
    float sum = 0.f;
    for (int i = tid; i < Ll; i += 256) {
        float e = __expf(x[i] - mx);
        w[i] = e;
        sum += e;
    }
    red[tid] = sum; __syncthreads();
    for (int s = 128; s; s >>= 1) { if (tid < s) red[tid] += red[tid+s]; __syncthreads(); }
    sum = red[0];
    int any = mx > -1e8f;
    if (tid == 0) g_hasany[bc] = any;
    float inv = any ? (1.f / sum) : 0.f;
    for (int i = tid; i < Ll; i += 256) w[i] *= inv;
}

// ---------------- zero contexts ----------------
__global__ void k_zeroctx() {
    int i = blockIdx.x * 256 + threadIdx.x;
    if (i < Bb*Cc*Hh) g_ctx[i] = 0.f;
}

// ---------------- contexts via tf32 (unchanged from R7) ----------------
#define CTX_AP 36
#define CTX_BP 72
__global__ __launch_bounds__(256) void k_ctx_tf32(const float* __restrict__ Hd,
                                                  const float* __restrict__ wts) {
    __shared__ float As[2][64*CTX_AP];
    __shared__ float Bs[2][32*CTX_BP];
    int b  = blockIdx.z;
    int h0 = blockIdx.x * 64;
    int l0 = blockIdx.y * 1024;
    int tid = threadIdx.x, lane = tid & 31, wid = tid >> 5;
    int wm = wid >> 2, wn = wid & 3;
    int g = lane >> 2, tq = lane & 3;
    const float* wb = wts + (size_t)b * Cc * Ll;
    const float* hb = Hd  + (size_t)b * Ll * Hh;

    uint32_t sA0 = smem_u32(&As[0][0]), sA1 = smem_u32(&As[1][0]);
    uint32_t sB0 = smem_u32(&Bs[0][0]), sB1 = smem_u32(&Bs[1][0]);

    {
        #pragma unroll
        for (int u = 0; u < 2; u++) {
            int e = u*256 + tid;
            int c = e >> 3, kq = e & 7;
            cpasync16(sA0 + (c*CTX_AP + kq*4)*4, &wb[(size_t)c * Ll + l0 + kq*4]);
        }
        #pragma unroll
        for (int u = 0; u < 2; u++) {
            int e = u*256 + tid;
            int kk = e >> 4, nq = e & 15;
            cpasync16(sB0 + (kk*CTX_BP + nq*4)*4, &hb[(size_t)(l0 + kk) * Hh + h0 + nq*4]);
        }
        cp_commit();
    }

    float acc[2][2][4] = {};
    for (int s = 0; s < 32; s++) {
        cp_wait<0>();
        __syncthreads();
        int buf = s & 1;
        if (s < 31) {
            int k0 = l0 + (s + 1) * 32;
            uint32_t dA = (buf ? sA0 : sA1), dB = (buf ? sB0 : sB1);
            #pragma unroll
            for (int u = 0; u < 2; u++) {
                int e = u*256 + tid;
                int c = e >> 3, kq = e & 7;
                cpasync16(dA + (c*CTX_AP + kq*4)*4, &wb[(size_t)c * Ll + k0 + kq*4]);
            }
            #pragma unroll
            for (int u = 0; u < 2; u++) {
                int e = u*256 + tid;
                int kk = e >> 4, nq = e & 15;
                cpasync16(dB + (kk*CTX_BP + nq*4)*4, &hb[(size_t)(k0 + kk) * Hh + h0 + nq*4]);
            }
            cp_commit();
        }
        const float* Ab = As[buf];
        const float* Bbuf = Bs[buf];
        #pragma unroll
        for (int ks = 0; ks < 4; ks++) {
            int kb = ks * 8;
            uint32_t af[2][4], bf[2][2];
            #pragma unroll
            for (int mt = 0; mt < 2; mt++) {
                int m = wm*32 + mt*16;
                af[mt][0] = f2tf32(Ab[(m + g    )*CTX_AP + kb + tq    ]);
                af[mt][1] = f2tf32(Ab[(m + g + 8)*CTX_AP + kb + tq    ]);
                af[mt][2] = f2tf32(Ab[(m + g    )*CTX_AP + kb + tq + 4]);
                af[mt][3] = f2tf32(Ab[(m + g + 8)*CTX_AP + kb + tq + 4]);
            }
            #pragma unroll
            for (int nt = 0; nt < 2; nt++) {
                int n = wn*16 + nt*8;
                bf[nt][0] = f2tf32(Bbuf[(kb + tq    )*CTX_BP + n + g]);
                bf[nt][1] = f2tf32(Bbuf[(kb + tq + 4)*CTX_BP + n + g]);
            }
            #pragma unroll
            for (int mt = 0; mt < 2; mt++)
                #pragma unroll
                for (int nt = 0; nt < 2; nt++)
                    mma_tf32(acc[mt][nt], af[mt], bf[nt]);
        }
    }
    #pragma unroll
    for (int mt = 0; mt < 2; mt++)
        #pragma unroll
        for (int nt = 0; nt < 2; nt++) {
            int m = wm*32 + mt*16 + g;
            int n = h0 + wn*16 + nt*8 + tq*2;
            float* base0 = &g_ctx[((size_t)(b*Cc + m)) * Hh + n];
            atomicAdd(base0,     acc[mt][nt][0]);
            atomicAdd(base0 + 1, acc[mt][nt][1]);
            float* base1 = &g_ctx[((size_t)(b*Cc + m + 8)) * Hh + n];
            atomicAdd(base1,     acc[mt][nt][2]);
            atomicAdd(base1 + 1, acc[mt][nt][3]);
        }
}

// ---------------- fallback for empty channels ----------------
__global__ void k_ctxfix(const float* __restrict__ Hd) {
    int i = blockIdx.x * 256 + threadIdx.x;
    if (i >= Bb*Cc*Hh) return;
    int bc = i >> 9;
    int h  = i & 511;
    if (!g_hasany[bc]) {
        int b = bc >> 6;
        g_ctx[i] = Hd[((size_t)(b*Ll + (Ll-1))) * Hh + h];
    }
}

// ---------------- final v3: tf32 MMA mix @ ctx ----------------
#define FP 72
__global__ __launch_bounds__(256) void k_final3(const float* __restrict__ Hd,
                                                const float* __restrict__ act,
                                                const int* __restrict__ cnt,
                                                const int* __restrict__ msk,
                                                float* __restrict__ out) {
    __shared__ float s[64*FP];     // mix [l][c]
    __shared__ float ct[64*FP];    // ctx [c][h]
    __shared__ float gate[64];
    __shared__ int   mk[64];
    int b  = blockIdx.y;
    int l0 = blockIdx.x * 64;
    int tid = threadIdx.x, lane = tid & 31, wid = tid >> 5;
    int wm = wid >> 2, wn = wid & 3;    // warp tile 32l x 16h
    int g = lane >> 2, tq = lane & 3;

    #pragma unroll
    for (int u = 0; u < 4; u++) {
        int e = u * 256 + tid;          // 1024 float4 units (64l x 16)
        int l = e >> 4, c4 = e & 15;
        float4 v = *(const float4*)&act[((size_t)(b*Ll + l0 + l)) * Cc + c4*4];
        s[l*FP + c4*4 + 0] = fmaxf(v.x, 0.f);
        s[l*FP + c4*4 + 1] = fmaxf(v.y, 0.f);
        s[l*FP + c4*4 + 2] = fmaxf(v.z, 0.f);
        s[l*FP + c4*4 + 3] = fmaxf(v.w, 0.f);
    }
    __syncthreads();
    if (tid < 64) {
        float sum = 0.f;
        #pragma unroll 8
        for (int c = 0; c < 64; c++) sum += s[tid*FP + c];
        float inv = 1.f / fmaxf(sum, 1.f);
        #pragma unroll 8
        for (int c = 0; c < 64; c++) s[tid*FP + c] *= inv;
        int gi = b*Ll + l0 + tid;
        gate[tid] = 1.f + (float)cnt[gi] / fmaxf((float)g_maxi[b], 1.f);
        mk[tid] = msk[gi];
    }
    __syncthreads();

    for (int h0 = 0; h0 < Hh; h0 += 64) {
        #pragma unroll
        for (int u = 0; u < 4; u++) {
            int e = u * 256 + tid;      // 1024 float4 units (64c x 16)
            int c = e >> 4, h4 = e & 15;
            float4 v = *(const float4*)&g_ctx[((size_t)(b*Cc + c)) * Hh + h0 + h4*4];
            *(float4*)&ct[c*FP + h4*4] = v;
        }
        __syncthreads();
        float acc[2][2][4] = {};
        #pragma unroll
        for (int ks = 0; ks < 8; ks++) {
            int kb = ks * 8;
            uint32_t af[2][4], bf[2][2];
            #pragma unroll
            for (int mt = 0; mt < 2; mt++) {
                int m = wm*32 + mt*16;
                af[mt][0] = f2tf32(s[(m + g    )*FP + kb + tq    ]);
                af[mt][1] = f2tf32(s[(m + g + 8)*FP + kb + tq    ]);
                af[mt][2] = f2tf32(s[(m + g    )*FP + kb + tq + 4]);
                af[mt][3] = f2tf32(s[(m + g + 8)*FP + kb + tq + 4]);
            }
            #pragma unroll
            for (int nt = 0; nt < 2; nt++) {
                int n = wn*16 + nt*8;
                bf[nt][0] = f2tf32(ct[(kb + tq    )*FP + n + g]);
                bf[nt][1] = f2tf32(ct[(kb + tq + 4)*FP + n + g]);
            }
            #pragma unroll
            for (int mt = 0; mt < 2; mt++)
                #pragma unroll
                for (int nt = 0; nt < 2; nt++)
                    mma_tf32(acc[mt][nt], af[mt], bf[nt]);
        }
        #pragma unroll
        for (int mt = 0; mt < 2; mt++) {
            int l = wm*32 + mt*16 + g;
            int gi0 = b*Ll + l0 + l;
            float g0 = gate[l];     bool m0 = mk[l] != 0;
            float g1 = gate[l+8];   bool m1 = mk[l+8] != 0;
            #pragma unroll
            for (int nt = 0; nt < 2; nt++) {
                int n = h0 + wn*16 + nt*8 + tq*2;
                size_t o0 = (size_t)gi0 * Hh + n;
                out[o0]   = m0 ? acc[mt][nt][0] * g0 : Hd[o0];
                out[o0+1] = m0 ? acc[mt][nt][1] * g0 : Hd[o0+1];
                size_t o1 = (size_t)(gi0 + 8) * Hh + n;
                out[o1]   = m1 ? acc[mt][nt][2] * g1 : Hd[o1];
                out[o1+1] = m1 ? acc[mt][nt][3] * g1 : Hd[o1+1];
            }
        }
        __syncthreads();
    }
}

// ---------------- launch ----------------
extern "C" void kernel_launch(void* const* d_in, const int* in_sizes, int n_in,
                              void* d_out, int out_size) {
    const float* hidden = (const float*)d_in[0];
    const int*   mask   = (const int*)d_in[1];
    const int*   cnt    = (const int*)d_in[2];
    const float* act    = (const float*)d_in[3];
    const float* pw     = (const float*)d_in[4];
    const float* pb     = (const float*)d_in[5];
    const float* sw     = (const float*)d_in[6];
    const float* sb     = (const float*)d_in[7];
    float* out  = (float*)d_out;
    float* wout = out + OUT_ATT;

    static bool attr_done = false;
    if (!attr_done) {
        cudaFuncSetAttribute(k_gemm1_v4, cudaFuncAttributeMaxDynamicSharedMemorySize, GEMM_SMEM);
        attr_done = true;
    }

    k_cvt_wT<<<dim3(Aa/32, Aa/32), dim3(32,32)>>>(pw);
    k_maxcount<<<Bb*8, 512>>>(cnt);
    k_gemm1_v4<<<BL/GM, 256, GEMM_SMEM>>>(hidden, pb, sw, cnt, sb);
    k_chlogits<<<Bb*(Ll/64), 256>>>(act);
    k_softmax<<<Bb*Cc, 256>>>(wout);
    k_zeroctx<<<(Bb*Cc*Hh+255)/256, 256>>>();
    k_ctx_tf32<<<dim3(Hh/64, Ll/1024, Bb), 256>>>(hidden, wout);
    k_ctxfix<<<(Bb*Cc*Hh+255)/256, 256>>>(hidden);
    k_final3<<<dim3(Ll/64, Bb), 256>>>(hidden, act, cnt, mask, out);
}